// round 3
// baseline (speedup 1.0000x reference)
#include <cuda_runtime.h>
#include <math.h>

#define NTOK 8192
#define DIN  768
#define HDIM 256
#define NEXP 8
#define CDIM 64
#define TOUT 512
#define EPSV 2.2204460492503131e-16f

// ---------------- static device scratch (allocation-free rule) ----------------
__device__ int   g_cnt[NEXP];
__device__ int   g_tok[NEXP * NTOK];
__device__ float g_gate[NEXP * NTOK];
__device__ float g_H[(size_t)NEXP * NTOK * HDIM];   // 64 MB: relu(fc1) rows per (expert, slot)
__device__ float g_O[(size_t)NEXP * NTOK * CDIM];   // 16 MB: gate-scaled fc2 rows

// ---------------- kernel 0: zero output + counts ----------------
__global__ void zero_kernel(float* __restrict__ y) {
    const int n = NTOK * TOUT;
    for (int i = blockIdx.x * blockDim.x + threadIdx.x; i < n;
         i += gridDim.x * blockDim.x)
        y[i] = 0.f;
    if (blockIdx.x == 0 && threadIdx.x < NEXP) g_cnt[threadIdx.x] = 0;
}

// ---------------- kernel 1: gating (one warp per token) ----------------
__global__ __launch_bounds__(256) void gate_kernel(const float* __restrict__ x,
                                                   const float* __restrict__ wg) {
    const int tok  = (blockIdx.x * blockDim.x + threadIdx.x) >> 5;
    const int lane = threadIdx.x & 31;
    if (tok >= NTOK) return;
    const float* xr = x + (size_t)tok * DIN;

    float acc[8];
#pragma unroll
    for (int e = 0; e < 8; e++) acc[e] = 0.f;

#pragma unroll
    for (int it = 0; it < DIN / 32; it++) {
        const int d = it * 32 + lane;
        const float xv = xr[d];
        const float4 w0 = *(const float4*)(wg + d * 8);
        const float4 w1 = *(const float4*)(wg + d * 8 + 4);
        acc[0] += xv * w0.x; acc[1] += xv * w0.y;
        acc[2] += xv * w0.z; acc[3] += xv * w0.w;
        acc[4] += xv * w1.x; acc[5] += xv * w1.y;
        acc[6] += xv * w1.z; acc[7] += xv * w1.w;
    }
#pragma unroll
    for (int e = 0; e < 8; e++)
#pragma unroll
        for (int off = 16; off; off >>= 1)
            acc[e] += __shfl_xor_sync(0xFFFFFFFFu, acc[e], off);

    if (lane == 0) {
        // top-1 (first index on tie, matching jax top_k)
        int i0 = 0; float v0 = acc[0];
#pragma unroll
        for (int e = 1; e < 8; e++) if (acc[e] > v0) { v0 = acc[e]; i0 = e; }
        // top-2
        int i1 = -1; float v1 = -3.4e38f;
#pragma unroll
        for (int e = 0; e < 8; e++)
            if (e != i0 && acc[e] > v1) { v1 = acc[e]; i1 = e; }
        // softmax over {v0, v1}, v1 <= v0
        const float t  = expf(v1 - v0);
        const float g0 = 1.f / (1.f + t);
        const float g1 = t / (1.f + t);

        int s0 = atomicAdd(&g_cnt[i0], 1);
        g_tok[i0 * NTOK + s0]  = tok;
        g_gate[i0 * NTOK + s0] = g0;
        int s1 = atomicAdd(&g_cnt[i1], 1);
        g_tok[i1 * NTOK + s1]  = tok;
        g_gate[i1 * NTOK + s1] = g1;
    }
}

// ---------------- kernel 2: fc1 grouped GEMM + bias + relu ----------------
// per expert e: H[s, n] = relu( sum_k x[tok(s), k] * W1[e, n, k] + b1[e, n] )
// Tile: 128(M) x 64(N) x 16(K), 256 threads, 8x4 microtile.
__global__ __launch_bounds__(256) void fc1_kernel(const float* __restrict__ x,
                                                  const float* __restrict__ W1,
                                                  const float* __restrict__ b1) {
    const int e   = blockIdx.z;
    const int cnt = g_cnt[e];
    const int m0  = blockIdx.x * 128;
    if (m0 >= cnt) return;
    const int n0 = blockIdx.y * 64;

    __shared__ float As[16][128];
    __shared__ float Bs[16][64];

    const int tid = threadIdx.x;
    // A-load mapping: 128 rows x 16 k; each thread loads 8 consecutive k of one row
    const int am = tid & 127;
    const int ak = (tid >> 7) * 8;
    const int arow = m0 + am;
    const int tokr = (arow < cnt) ? g_tok[e * NTOK + arow] : 0;
    const float* aptr = x + (size_t)tokr * DIN;
    // B-load mapping: 64 rows(n) x 16 k; each thread loads 4 consecutive k
    const int bn = tid & 63;
    const int bk = (tid >> 6) * 4;
    const float* bptr = W1 + ((size_t)e * HDIM + n0 + bn) * DIN;
    // compute mapping: 16x16 thread grid; rows ty*8.., cols tx*4..
    const int tx = tid & 15;
    const int ty = tid >> 4;

    float acc[8][4];
#pragma unroll
    for (int i = 0; i < 8; i++)
#pragma unroll
        for (int j = 0; j < 4; j++) acc[i][j] = 0.f;

    for (int k0 = 0; k0 < DIN; k0 += 16) {
        const float4 a0 = *(const float4*)(aptr + k0 + ak);
        const float4 a1 = *(const float4*)(aptr + k0 + ak + 4);
        const float4 bv = *(const float4*)(bptr + k0 + bk);
        __syncthreads();
        As[ak + 0][am] = a0.x; As[ak + 1][am] = a0.y;
        As[ak + 2][am] = a0.z; As[ak + 3][am] = a0.w;
        As[ak + 4][am] = a1.x; As[ak + 5][am] = a1.y;
        As[ak + 6][am] = a1.z; As[ak + 7][am] = a1.w;
        Bs[bk + 0][bn] = bv.x; Bs[bk + 1][bn] = bv.y;
        Bs[bk + 2][bn] = bv.z; Bs[bk + 3][bn] = bv.w;
        __syncthreads();
#pragma unroll
        for (int k = 0; k < 16; k++) {
            const float4 av0 = *(const float4*)&As[k][ty * 8];
            const float4 av1 = *(const float4*)&As[k][ty * 8 + 4];
            const float4 bvv = *(const float4*)&Bs[k][tx * 4];
            const float a[8] = {av0.x, av0.y, av0.z, av0.w, av1.x, av1.y, av1.z, av1.w};
            const float b[4] = {bvv.x, bvv.y, bvv.z, bvv.w};
#pragma unroll
            for (int i = 0; i < 8; i++)
#pragma unroll
                for (int j = 0; j < 4; j++) acc[i][j] += a[i] * b[j];
        }
    }

    const int nb = n0 + tx * 4;
    const float4 bb = *(const float4*)(b1 + e * HDIM + nb);
#pragma unroll
    for (int i = 0; i < 8; i++) {
        const int m = m0 + ty * 8 + i;
        if (m < cnt) {
            float4 r;
            r.x = fmaxf(acc[i][0] + bb.x, 0.f);
            r.y = fmaxf(acc[i][1] + bb.y, 0.f);
            r.z = fmaxf(acc[i][2] + bb.z, 0.f);
            r.w = fmaxf(acc[i][3] + bb.w, 0.f);
            *(float4*)&g_H[((size_t)e * NTOK + m) * HDIM + nb] = r;
        }
    }
}

// ---------------- kernel 3: fc2 grouped GEMM + bias + gate pre-scale ----------------
// per expert e: O[s, c] = gate(s) * ( sum_k H[s, k] * W2[e, c, k] + b2[e, c] )
// Tile: 64 x 64 x 16, 256 threads, 4x4 microtile.
__global__ __launch_bounds__(256) void fc2_kernel(const float* __restrict__ W2,
                                                  const float* __restrict__ b2) {
    const int e   = blockIdx.y;
    const int cnt = g_cnt[e];
    const int m0  = blockIdx.x * 64;
    if (m0 >= cnt) return;

    __shared__ float As[16][64];
    __shared__ float Bs[16][64];

    const int tid = threadIdx.x;
    const int am = tid & 63;
    const int ak = (tid >> 6) * 4;
    const float* aptr = g_H + ((size_t)e * NTOK + m0 + am) * HDIM;  // rows beyond cnt: zero/stale, masked later
    const int bn = tid & 63;
    const int bk = (tid >> 6) * 4;
    const float* bptr = W2 + ((size_t)e * CDIM + bn) * HDIM;
    const int tx = tid & 15;
    const int ty = tid >> 4;

    float acc[4][4];
#pragma unroll
    for (int i = 0; i < 4; i++)
#pragma unroll
        for (int j = 0; j < 4; j++) acc[i][j] = 0.f;

    for (int k0 = 0; k0 < HDIM; k0 += 16) {
        const float4 a0 = *(const float4*)(aptr + k0 + ak);
        const float4 bv = *(const float4*)(bptr + k0 + bk);
        __syncthreads();
        As[ak + 0][am] = a0.x; As[ak + 1][am] = a0.y;
        As[ak + 2][am] = a0.z; As[ak + 3][am] = a0.w;
        Bs[bk + 0][bn] = bv.x; Bs[bk + 1][bn] = bv.y;
        Bs[bk + 2][bn] = bv.z; Bs[bk + 3][bn] = bv.w;
        __syncthreads();
#pragma unroll
        for (int k = 0; k < 16; k++) {
            const float4 av = *(const float4*)&As[k][ty * 4];
            const float4 bvv = *(const float4*)&Bs[k][tx * 4];
            const float a[4] = {av.x, av.y, av.z, av.w};
            const float b[4] = {bvv.x, bvv.y, bvv.z, bvv.w};
#pragma unroll
            for (int i = 0; i < 4; i++)
#pragma unroll
                for (int j = 0; j < 4; j++) acc[i][j] += a[i] * b[j];
        }
    }

    const int cb = tx * 4;
    const float4 bb = *(const float4*)(b2 + e * CDIM + cb);
#pragma unroll
    for (int i = 0; i < 4; i++) {
        const int s = m0 + ty * 4 + i;
        if (s < cnt) {
            const float g = g_gate[e * NTOK + s];
            float4 r;
            r.x = (acc[i][0] + bb.x) * g;
            r.y = (acc[i][1] + bb.y) * g;
            r.z = (acc[i][2] + bb.z) * g;
            r.w = (acc[i][3] + bb.w) * g;
            *(float4*)&g_O[((size_t)e * NTOK + s) * CDIM + cb] = r;
        }
    }
}

// ---------------- kernel 4: combine GEMM + atomic scatter into y ----------------
// per expert e: y[tok(s), t] += sum_c O[s, c] * Wm[e, t, c]
// Tile: 64 x 64 x 16 (K=64 total), 256 threads, 4x4 microtile.
__global__ __launch_bounds__(256) void combine_kernel(const float* __restrict__ Wm,
                                                      float* __restrict__ y) {
    const int e   = blockIdx.z;
    const int cnt = g_cnt[e];
    const int m0  = blockIdx.x * 64;
    if (m0 >= cnt) return;
    const int n0 = blockIdx.y * 64;

    __shared__ float As[16][64];
    __shared__ float Bs[16][64];

    const int tid = threadIdx.x;
    const int am = tid & 63;
    const int ak = (tid >> 6) * 4;
    const float* aptr = g_O + ((size_t)e * NTOK + m0 + am) * CDIM;
    const int bn = tid & 63;
    const int bk = (tid >> 6) * 4;
    const float* bptr = Wm + ((size_t)e * TOUT + n0 + bn) * CDIM;
    const int tx = tid & 15;
    const int ty = tid >> 4;

    float acc[4][4];
#pragma unroll
    for (int i = 0; i < 4; i++)
#pragma unroll
        for (int j = 0; j < 4; j++) acc[i][j] = 0.f;

    for (int k0 = 0; k0 < CDIM; k0 += 16) {
        const float4 a0 = *(const float4*)(aptr + k0 + ak);
        const float4 bv = *(const float4*)(bptr + k0 + bk);
        __syncthreads();
        As[ak + 0][am] = a0.x; As[ak + 1][am] = a0.y;
        As[ak + 2][am] = a0.z; As[ak + 3][am] = a0.w;
        Bs[bk + 0][bn] = bv.x; Bs[bk + 1][bn] = bv.y;
        Bs[bk + 2][bn] = bv.z; Bs[bk + 3][bn] = bv.w;
        __syncthreads();
#pragma unroll
        for (int k = 0; k < 16; k++) {
            const float4 av = *(const float4*)&As[k][ty * 4];
            const float4 bvv = *(const float4*)&Bs[k][tx * 4];
            const float a[4] = {av.x, av.y, av.z, av.w};
            const float b[4] = {bvv.x, bvv.y, bvv.z, bvv.w};
#pragma unroll
            for (int i = 0; i < 4; i++)
#pragma unroll
                for (int j = 0; j < 4; j++) acc[i][j] += a[i] * b[j];
        }
    }

    const int tb = n0 + tx * 4;
#pragma unroll
    for (int i = 0; i < 4; i++) {
        const int s = m0 + ty * 4 + i;
        if (s < cnt) {
            const int tok = g_tok[e * NTOK + s];
            float* yr = y + (size_t)tok * TOUT + tb;
#pragma unroll
            for (int j = 0; j < 4; j++) atomicAdd(yr + j, acc[i][j]);
        }
    }
}

// ---------------- kernel 5: EPS fixup (reference's where(y==0, eps, y)) ----------------
__global__ void eps_kernel(float* __restrict__ y) {
    const int n = NTOK * TOUT;
    for (int i = blockIdx.x * blockDim.x + threadIdx.x; i < n;
         i += gridDim.x * blockDim.x) {
        const float v = y[i];
        if (v == 0.f) y[i] = EPSV;
    }
}

// ---------------- launch ----------------
extern "C" void kernel_launch(void* const* d_in, const int* in_sizes, int n_in,
                              void* d_out, int out_size) {
    const float* x  = (const float*)d_in[0];
    // d_in[1] = labels (int64) — unused by the reference computation
    const float* wg = (const float*)d_in[2];
    const float* W1 = (const float*)d_in[3];
    const float* b1 = (const float*)d_in[4];
    const float* W2 = (const float*)d_in[5];
    const float* b2 = (const float*)d_in[6];
    const float* Wm = (const float*)d_in[7];
    float* y = (float*)d_out;

    zero_kernel<<<256, 256>>>(y);
    gate_kernel<<<NTOK / 8, 256>>>(x, wg);

    dim3 g2(NTOK / 128, HDIM / 64, NEXP);   // (64, 4, 8)
    fc1_kernel<<<g2, 256>>>(x, W1, b1);

    dim3 g3(NTOK / 64, NEXP);               // (128, 8)
    fc2_kernel<<<g3, 256>>>(W2, b2);

    dim3 g4(NTOK / 64, TOUT / 64, NEXP);    // (128, 8, 8)
    combine_kernel<<<g4, 256>>>(Wm, y);

    eps_kernel<<<512, 256>>>(y);
}

// round 5
// speedup vs baseline: 1.7342x; 1.7342x over previous
#include <cuda_runtime.h>
#include <cuda_bf16.h>
#include <math.h>
#include <stdint.h>

#define NTOK 8192
#define DIN  768
#define HDIM 256
#define NEXP 8
#define CDIM 64
#define TOUT 512
#define EPSV 2.2204460492503131e-16f

// ---------------- static device scratch (allocation-free rule) ----------------
__device__ int   g_cnt[NEXP];
__device__ int   g_tok[NEXP * NTOK];
__device__ float g_gate[NEXP * NTOK];

__device__ __nv_bfloat16 g_xhi[NTOK * DIN],        g_xlo[NTOK * DIN];
__device__ __nv_bfloat16 g_w1hi[NEXP * HDIM * DIN], g_w1lo[NEXP * HDIM * DIN];
__device__ __nv_bfloat16 g_w2hi[NEXP * CDIM * HDIM], g_w2lo[NEXP * CDIM * HDIM];
__device__ __nv_bfloat16 g_wmhi[NEXP * TOUT * CDIM], g_wmlo[NEXP * TOUT * CDIM];
__device__ __nv_bfloat16 g_Hhi[(size_t)NEXP * NTOK * HDIM], g_Hlo[(size_t)NEXP * NTOK * HDIM];
__device__ __nv_bfloat16 g_Ohi[(size_t)NEXP * NTOK * CDIM], g_Olo[(size_t)NEXP * NTOK * CDIM];

// ---------------- small helpers ----------------
__device__ __forceinline__ uint32_t cvta_smem(const void* p) {
    return (uint32_t)__cvta_generic_to_shared(p);
}
__device__ __forceinline__ void ldmx4(uint32_t* r, uint32_t addr) {
    asm volatile("ldmatrix.sync.aligned.m8n8.x4.shared.b16 {%0,%1,%2,%3}, [%4];\n"
                 : "=r"(r[0]), "=r"(r[1]), "=r"(r[2]), "=r"(r[3]) : "r"(addr));
}
__device__ __forceinline__ void mma16816(float* c, const uint32_t* a, uint32_t b0, uint32_t b1) {
    asm volatile(
        "mma.sync.aligned.m16n8k16.row.col.f32.bf16.bf16.f32 "
        "{%0,%1,%2,%3}, {%4,%5,%6,%7}, {%8,%9}, {%0,%1,%2,%3};\n"
        : "+f"(c[0]), "+f"(c[1]), "+f"(c[2]), "+f"(c[3])
        : "r"(a[0]), "r"(a[1]), "r"(a[2]), "r"(a[3]), "r"(b0), "r"(b1));
}
__device__ __forceinline__ void split_store2(__nv_bfloat16* hi, __nv_bfloat16* lo,
                                             size_t off, float v0, float v1) {
    __nv_bfloat16 h0 = __float2bfloat16_rn(v0), h1 = __float2bfloat16_rn(v1);
    __nv_bfloat162 th; th.x = h0; th.y = h1;
    __nv_bfloat162 tl;
    tl.x = __float2bfloat16_rn(v0 - __bfloat162float(h0));
    tl.y = __float2bfloat16_rn(v1 - __bfloat162float(h1));
    *(__nv_bfloat162*)(hi + off) = th;
    *(__nv_bfloat162*)(lo + off) = tl;
}

// ---------------- shared tile (block = 128M x 64N x 32K, hi/lo) ----------------
struct __align__(16) SmemMMA {
    __nv_bfloat16 A[2][128][40];   // [split][row][k], pad 32->40 (conflict-free ldmatrix)
    __nv_bfloat16 B[2][64][40];
};

// ---------------- shared mainloop ----------------
// acc[mf 0..3][nf 0..1][4]; warp grid 2(M) x 4(N); per-warp tile 64x16.
// A/B thread gmem pointers are pre-offset to (row, k=0 + this thread's k-seg).
template <int NCH>
__device__ __forceinline__ void run_mainloop(
    SmemMMA& sm,
    const __nv_bfloat16* aghi, const __nv_bfloat16* aglo,
    const __nv_bfloat16* bghi, const __nv_bfloat16* bglo,
    float (&acc)[4][2][4])
{
    const int tid  = threadIdx.x;
    const int lane = tid & 31;
    const int wid  = tid >> 5;
    const int warp_m = wid & 1;
    const int warp_n = wid >> 1;
    const int arow = tid >> 1, acol = (tid & 1) * 16;
    const int brow = tid >> 2, bcol = (tid & 3) * 8;

    // per-lane ldmatrix base addresses
    uint32_t aaddr[2], baddr[2];
    {
        const int ar = warp_m * 64 + ((lane >> 3) & 1) * 8 + (lane & 7);
        const int ac = (lane >> 4) * 8;
        aaddr[0] = cvta_smem(&sm.A[0][ar][ac]);
        aaddr[1] = cvta_smem(&sm.A[1][ar][ac]);
        const int br = warp_n * 16 + ((lane >> 4) << 3) + (lane & 7);
        const int bc = ((lane >> 3) & 1) * 8;
        baddr[0] = cvta_smem(&sm.B[0][br][bc]);
        baddr[1] = cvta_smem(&sm.B[1][br][bc]);
    }

    uint4 ra[2][2], rb[2];
    ra[0][0] = *(const uint4*)(aghi);     ra[0][1] = *(const uint4*)(aghi + 8);
    ra[1][0] = *(const uint4*)(aglo);     ra[1][1] = *(const uint4*)(aglo + 8);
    rb[0]    = *(const uint4*)(bghi);     rb[1]    = *(const uint4*)(bglo);

    for (int ch = 0; ch < NCH; ch++) {
        __syncthreads();
        *(uint4*)&sm.A[0][arow][acol]     = ra[0][0];
        *(uint4*)&sm.A[0][arow][acol + 8] = ra[0][1];
        *(uint4*)&sm.A[1][arow][acol]     = ra[1][0];
        *(uint4*)&sm.A[1][arow][acol + 8] = ra[1][1];
        *(uint4*)&sm.B[0][brow][bcol]     = rb[0];
        *(uint4*)&sm.B[1][brow][bcol]     = rb[1];
        __syncthreads();

        if (ch + 1 < NCH) {
            aghi += 32; aglo += 32; bghi += 32; bglo += 32;
            ra[0][0] = *(const uint4*)(aghi);  ra[0][1] = *(const uint4*)(aghi + 8);
            ra[1][0] = *(const uint4*)(aglo);  ra[1][1] = *(const uint4*)(aglo + 8);
            rb[0]    = *(const uint4*)(bghi);  rb[1]    = *(const uint4*)(bglo);
        }

#pragma unroll
        for (int kk = 0; kk < 2; kk++) {
            uint32_t bh[4], bl[4];
            ldmx4(bh, baddr[0] + kk * 32);
            ldmx4(bl, baddr[1] + kk * 32);
#pragma unroll
            for (int mf = 0; mf < 4; mf++) {
                uint32_t ah[4], al[4];
                ldmx4(ah, aaddr[0] + (uint32_t)(mf * 16 * 80) + kk * 32);
                ldmx4(al, aaddr[1] + (uint32_t)(mf * 16 * 80) + kk * 32);
#pragma unroll
                for (int nf = 0; nf < 2; nf++) {
                    mma16816(acc[mf][nf], ah, bh[2 * nf], bh[2 * nf + 1]);
                    mma16816(acc[mf][nf], ah, bl[2 * nf], bl[2 * nf + 1]);
                    mma16816(acc[mf][nf], al, bh[2 * nf], bh[2 * nf + 1]);
                }
            }
        }
    }
}

// ---------------- kernel 0: zero output + counts ----------------
__global__ void zero_kernel(float* __restrict__ y) {
    const int n = NTOK * TOUT;
    for (int i = blockIdx.x * blockDim.x + threadIdx.x; i < n;
         i += gridDim.x * blockDim.x)
        y[i] = 0.f;
    if (blockIdx.x == 0 && threadIdx.x < NEXP) g_cnt[threadIdx.x] = 0;
}

// ---------------- kernel 0b: split all fp32 operands into bf16 hi/lo ----------------
__global__ void split_all_kernel(const float* __restrict__ x,  const float* __restrict__ W1,
                                 const float* __restrict__ W2, const float* __restrict__ Wm) {
    const int stride = gridDim.x * blockDim.x;
    const int t = blockIdx.x * blockDim.x + threadIdx.x;
#define SPLIT_LOOP(SRC, HI, LO, N)                                   \
    for (int i = t; i < (N); i += stride) {                          \
        const float v = SRC[i];                                      \
        const __nv_bfloat16 h = __float2bfloat16_rn(v);              \
        HI[i] = h;                                                   \
        LO[i] = __float2bfloat16_rn(v - __bfloat162float(h));        \
    }
    SPLIT_LOOP(x,  g_xhi,  g_xlo,  NTOK * DIN)
    SPLIT_LOOP(W1, g_w1hi, g_w1lo, NEXP * HDIM * DIN)
    SPLIT_LOOP(W2, g_w2hi, g_w2lo, NEXP * CDIM * HDIM)
    SPLIT_LOOP(Wm, g_wmhi, g_wmlo, NEXP * TOUT * CDIM)
#undef SPLIT_LOOP
}

// ---------------- kernel 1: gating (one warp per token) ----------------
__global__ __launch_bounds__(256) void gate_kernel(const float* __restrict__ x,
                                                   const float* __restrict__ wg) {
    const int tok  = (blockIdx.x * blockDim.x + threadIdx.x) >> 5;
    const int lane = threadIdx.x & 31;
    if (tok >= NTOK) return;
    const float* xr = x + (size_t)tok * DIN;

    float acc[8];
#pragma unroll
    for (int e = 0; e < 8; e++) acc[e] = 0.f;

#pragma unroll
    for (int it = 0; it < DIN / 32; it++) {
        const int d = it * 32 + lane;
        const float xv = xr[d];
        const float4 w0 = *(const float4*)(wg + d * 8);
        const float4 w1 = *(const float4*)(wg + d * 8 + 4);
        acc[0] += xv * w0.x; acc[1] += xv * w0.y;
        acc[2] += xv * w0.z; acc[3] += xv * w0.w;
        acc[4] += xv * w1.x; acc[5] += xv * w1.y;
        acc[6] += xv * w1.z; acc[7] += xv * w1.w;
    }
#pragma unroll
    for (int e = 0; e < 8; e++)
#pragma unroll
        for (int off = 16; off; off >>= 1)
            acc[e] += __shfl_xor_sync(0xFFFFFFFFu, acc[e], off);

    if (lane == 0) {
        int i0 = 0; float v0 = acc[0];
#pragma unroll
        for (int e = 1; e < 8; e++) if (acc[e] > v0) { v0 = acc[e]; i0 = e; }
        int i1 = -1; float v1 = -3.4e38f;
#pragma unroll
        for (int e = 0; e < 8; e++)
            if (e != i0 && acc[e] > v1) { v1 = acc[e]; i1 = e; }
        const float tt = expf(v1 - v0);
        const float g0 = 1.f / (1.f + tt);
        const float g1 = tt / (1.f + tt);

        int s0 = atomicAdd(&g_cnt[i0], 1);
        g_tok[i0 * NTOK + s0]  = tok;
        g_gate[i0 * NTOK + s0] = g0;
        int s1 = atomicAdd(&g_cnt[i1], 1);
        g_tok[i1 * NTOK + s1]  = tok;
        g_gate[i1 * NTOK + s1] = g1;
    }
}

// ---------------- kernel 2: fc1 (split-bf16 tensor GEMM) ----------------
// H[s,n] = relu( x[tok(s),:] . W1[e,n,:] + b1[e,n] ), stored as bf16 hi/lo
__global__ __launch_bounds__(256) void fc1_mma(const float* __restrict__ b1) {
    const int e   = blockIdx.z;
    const int cnt = g_cnt[e];
    const int m0  = blockIdx.x * 128;
    if (m0 >= cnt) return;
    const int n0  = blockIdx.y * 64;
    const int tid = threadIdx.x;

    __shared__ SmemMMA sm;

    const int arow = tid >> 1;
    int r = m0 + arow; if (r >= cnt) r = cnt - 1;
    const int tok = g_tok[e * NTOK + r];
    const __nv_bfloat16* aghi = g_xhi + (size_t)tok * DIN + (tid & 1) * 16;
    const __nv_bfloat16* aglo = g_xlo + (size_t)tok * DIN + (tid & 1) * 16;
    const int brow = tid >> 2;
    const __nv_bfloat16* bghi = g_w1hi + ((size_t)e * HDIM + n0 + brow) * DIN + (tid & 3) * 8;
    const __nv_bfloat16* bglo = g_w1lo + ((size_t)e * HDIM + n0 + brow) * DIN + (tid & 3) * 8;

    float acc[4][2][4] = {};
    run_mainloop<DIN / 32>(sm, aghi, aglo, bghi, bglo, acc);

    const int lane = tid & 31, wid = tid >> 5;
    const int warp_m = wid & 1, warp_n = wid >> 1;
#pragma unroll
    for (int nf = 0; nf < 2; nf++) {
        const int n = n0 + warp_n * 16 + nf * 8 + 2 * (lane & 3);
        const float bb0 = b1[e * HDIM + n];
        const float bb1 = b1[e * HDIM + n + 1];
#pragma unroll
        for (int mf = 0; mf < 4; mf++)
#pragma unroll
            for (int hr = 0; hr < 2; hr++) {
                const int m = m0 + warp_m * 64 + mf * 16 + (lane >> 2) + hr * 8;
                if (m < cnt) {
                    const float h0 = fmaxf(acc[mf][nf][2 * hr + 0] + bb0, 0.f);
                    const float h1 = fmaxf(acc[mf][nf][2 * hr + 1] + bb1, 0.f);
                    split_store2(g_Hhi, g_Hlo, ((size_t)e * NTOK + m) * HDIM + n, h0, h1);
                }
            }
    }
}

// ---------------- kernel 3: fc2 (split-bf16 tensor GEMM + gate) ----------------
// O[s,c] = gate(s) * ( H[s,:] . W2[e,c,:] + b2[e,c] ), stored as bf16 hi/lo
__global__ __launch_bounds__(256) void fc2_mma(const float* __restrict__ b2) {
    const int e   = blockIdx.z;
    const int cnt = g_cnt[e];
    const int m0  = blockIdx.x * 128;
    if (m0 >= cnt) return;
    const int tid = threadIdx.x;

    __shared__ SmemMMA sm;

    const int arow = tid >> 1;
    const __nv_bfloat16* aghi = g_Hhi + ((size_t)e * NTOK + m0 + arow) * HDIM + (tid & 1) * 16;
    const __nv_bfloat16* aglo = g_Hlo + ((size_t)e * NTOK + m0 + arow) * HDIM + (tid & 1) * 16;
    const int brow = tid >> 2;
    const __nv_bfloat16* bghi = g_w2hi + ((size_t)e * CDIM + brow) * HDIM + (tid & 3) * 8;
    const __nv_bfloat16* bglo = g_w2lo + ((size_t)e * CDIM + brow) * HDIM + (tid & 3) * 8;

    float acc[4][2][4] = {};
    run_mainloop<HDIM / 32>(sm, aghi, aglo, bghi, bglo, acc);

    const int lane = tid & 31, wid = tid >> 5;
    const int warp_m = wid & 1, warp_n = wid >> 1;
#pragma unroll
    for (int nf = 0; nf < 2; nf++) {
        const int n = warp_n * 16 + nf * 8 + 2 * (lane & 3);
        const float bb0 = b2[e * CDIM + n];
        const float bb1 = b2[e * CDIM + n + 1];
#pragma unroll
        for (int mf = 0; mf < 4; mf++)
#pragma unroll
            for (int hr = 0; hr < 2; hr++) {
                const int m = m0 + warp_m * 64 + mf * 16 + (lane >> 2) + hr * 8;
                if (m < cnt) {
                    const float g = g_gate[e * NTOK + m];
                    const float o0 = (acc[mf][nf][2 * hr + 0] + bb0) * g;
                    const float o1 = (acc[mf][nf][2 * hr + 1] + bb1) * g;
                    split_store2(g_Ohi, g_Olo, ((size_t)e * NTOK + m) * CDIM + n, o0, o1);
                }
            }
    }
}

// ---------------- kernel 4: combine (split-bf16 tensor GEMM + atomic scatter) ----------------
// y[tok(s), t] += O[s,:] . Wm[e,t,:]
__global__ __launch_bounds__(256) void combine_mma(const float* __restrict__ unused,
                                                   float* __restrict__ y) {
    const int e   = blockIdx.z;
    const int cnt = g_cnt[e];
    const int m0  = blockIdx.x * 128;
    if (m0 >= cnt) return;
    const int n0  = blockIdx.y * 64;
    const int tid = threadIdx.x;

    __shared__ SmemMMA sm;

    const int arow = tid >> 1;
    const __nv_bfloat16* aghi = g_Ohi + ((size_t)e * NTOK + m0 + arow) * CDIM + (tid & 1) * 16;
    const __nv_bfloat16* aglo = g_Olo + ((size_t)e * NTOK + m0 + arow) * CDIM + (tid & 1) * 16;
    const int brow = tid >> 2;
    const __nv_bfloat16* bghi = g_wmhi + ((size_t)e * TOUT + n0 + brow) * CDIM + (tid & 3) * 8;
    const __nv_bfloat16* bglo = g_wmlo + ((size_t)e * TOUT + n0 + brow) * CDIM + (tid & 3) * 8;

    float acc[4][2][4] = {};
    run_mainloop<CDIM / 32>(sm, aghi, aglo, bghi, bglo, acc);

    const int lane = tid & 31, wid = tid >> 5;
    const int warp_m = wid & 1, warp_n = wid >> 1;
#pragma unroll
    for (int mf = 0; mf < 4; mf++)
#pragma unroll
        for (int hr = 0; hr < 2; hr++) {
            const int m = m0 + warp_m * 64 + mf * 16 + (lane >> 2) + hr * 8;
            if (m < cnt) {
                const int tok = g_tok[e * NTOK + m];
                float* yr = y + (size_t)tok * TOUT;
#pragma unroll
                for (int nf = 0; nf < 2; nf++) {
                    const int n = n0 + warp_n * 16 + nf * 8 + 2 * (lane & 3);
                    atomicAdd(yr + n,     acc[mf][nf][2 * hr + 0]);
                    atomicAdd(yr + n + 1, acc[mf][nf][2 * hr + 1]);
                }
            }
        }
}

// ---------------- kernel 5: EPS fixup ----------------
__global__ void eps_kernel(float* __restrict__ y) {
    const int n = NTOK * TOUT;
    for (int i = blockIdx.x * blockDim.x + threadIdx.x; i < n;
         i += gridDim.x * blockDim.x) {
        const float v = y[i];
        if (v == 0.f) y[i] = EPSV;
    }
}

// ---------------- launch ----------------
extern "C" void kernel_launch(void* const* d_in, const int* in_sizes, int n_in,
                              void* d_out, int out_size) {
    const float* x  = (const float*)d_in[0];
    // d_in[1] = labels (int64) — unused by the reference computation
    const float* wg = (const float*)d_in[2];
    const float* W1 = (const float*)d_in[3];
    const float* b1 = (const float*)d_in[4];
    const float* W2 = (const float*)d_in[5];
    const float* b2 = (const float*)d_in[6];
    const float* Wm = (const float*)d_in[7];
    float* y = (float*)d_out;

    zero_kernel<<<256, 256>>>(y);
    split_all_kernel<<<2048, 256>>>(x, W1, W2, Wm);
    gate_kernel<<<NTOK / 8, 256>>>(x, wg);

    dim3 g1(NTOK / 128, HDIM / 64, NEXP);   // (64, 4, 8)
    fc1_mma<<<g1, 256>>>(b1);

    dim3 g2(NTOK / 128, 1, NEXP);           // (64, 1, 8)
    fc2_mma<<<g2, 256>>>(b2);

    dim3 g3(NTOK / 128, TOUT / 64, NEXP);   // (64, 8, 8)
    combine_mma<<<g3, 256>>>(nullptr, y);

    eps_kernel<<<512, 256>>>(y);
}

// round 6
// speedup vs baseline: 1.9299x; 1.1129x over previous
#include <cuda_runtime.h>
#include <cuda_bf16.h>
#include <math.h>
#include <stdint.h>

#define NTOK 8192
#define DIN  768
#define HDIM 256
#define NEXP 8
#define CDIM 64
#define TOUT 512
#define EPSV 2.2204460492503131e-16f

// ---------------- static device scratch (allocation-free rule) ----------------
__device__ int   g_cnt[NEXP];
__device__ int   g_tok[NEXP * NTOK];
__device__ float g_gate[NEXP * NTOK];

__device__ __nv_bfloat16 g_xhi[NTOK * DIN],        g_xlo[NTOK * DIN];
__device__ __nv_bfloat16 g_w1hi[NEXP * HDIM * DIN], g_w1lo[NEXP * HDIM * DIN];
__device__ __nv_bfloat16 g_w2hi[NEXP * CDIM * HDIM], g_w2lo[NEXP * CDIM * HDIM];
__device__ __nv_bfloat16 g_wmhi[NEXP * TOUT * CDIM], g_wmlo[NEXP * TOUT * CDIM];
__device__ __nv_bfloat16 g_Hhi[(size_t)NEXP * NTOK * HDIM], g_Hlo[(size_t)NEXP * NTOK * HDIM];
__device__ __nv_bfloat16 g_Ohi[(size_t)NEXP * NTOK * CDIM], g_Olo[(size_t)NEXP * NTOK * CDIM];

// ---------------- small helpers ----------------
__device__ __forceinline__ uint32_t cvta_smem(const void* p) {
    return (uint32_t)__cvta_generic_to_shared(p);
}
__device__ __forceinline__ void ldmx4(uint32_t* r, uint32_t addr) {
    asm volatile("ldmatrix.sync.aligned.m8n8.x4.shared.b16 {%0,%1,%2,%3}, [%4];\n"
                 : "=r"(r[0]), "=r"(r[1]), "=r"(r[2]), "=r"(r[3]) : "r"(addr));
}
__device__ __forceinline__ void mma16816(float* c, const uint32_t* a, uint32_t b0, uint32_t b1) {
    asm volatile(
        "mma.sync.aligned.m16n8k16.row.col.f32.bf16.bf16.f32 "
        "{%0,%1,%2,%3}, {%4,%5,%6,%7}, {%8,%9}, {%0,%1,%2,%3};\n"
        : "+f"(c[0]), "+f"(c[1]), "+f"(c[2]), "+f"(c[3])
        : "r"(a[0]), "r"(a[1]), "r"(a[2]), "r"(a[3]), "r"(b0), "r"(b1));
}
__device__ __forceinline__ void split_store2(__nv_bfloat16* hi, __nv_bfloat16* lo,
                                             size_t off, float v0, float v1) {
    __nv_bfloat16 h0 = __float2bfloat16_rn(v0), h1 = __float2bfloat16_rn(v1);
    __nv_bfloat162 th; th.x = h0; th.y = h1;
    __nv_bfloat162 tl;
    tl.x = __float2bfloat16_rn(v0 - __bfloat162float(h0));
    tl.y = __float2bfloat16_rn(v1 - __bfloat162float(h1));
    *(__nv_bfloat162*)(hi + off) = th;
    *(__nv_bfloat162*)(lo + off) = tl;
}

// ---------------- shared tile (block = 128M x BN x 32K, hi/lo) ----------------
template <int BN>
struct __align__(16) SmemT {
    __nv_bfloat16 A[2][128][40];   // [split][row][k], pad 32->40 (conflict-free ldmatrix)
    __nv_bfloat16 B[2][BN][40];
};

// ---------------- shared mainloop ----------------
// Warp grid 2(M) x 4(N); per-warp tile 64 x (BN/4). NF = BN/32 n-frags of 8.
// A/B thread gmem pointers pre-offset to (row, this thread's k-seg).
template <int NCH, int BN>
__device__ __forceinline__ void run_mainloop(
    SmemT<BN>& sm,
    const __nv_bfloat16* aghi, const __nv_bfloat16* aglo,
    const __nv_bfloat16* bghi, const __nv_bfloat16* bglo,
    float (&acc)[4][BN / 32][4])
{
    constexpr int NF = BN / 32;
    const int tid  = threadIdx.x;
    const int lane = tid & 31;
    const int wid  = tid >> 5;
    const int warp_m = wid & 1;
    const int warp_n = wid >> 1;
    const int arow = tid >> 1, acol = (tid & 1) * 16;
    const int brow = (BN == 128) ? (tid >> 1) : (tid >> 2);
    const int bcol = (BN == 128) ? (tid & 1) * 16 : (tid & 3) * 8;

    // per-lane ldmatrix base addresses
    uint32_t aaddr[2], baddr[2];
    {
        const int ar = warp_m * 64 + ((lane >> 3) & 1) * 8 + (lane & 7);
        const int ac = (lane >> 4) * 8;
        aaddr[0] = cvta_smem(&sm.A[0][ar][ac]);
        aaddr[1] = cvta_smem(&sm.A[1][ar][ac]);
        const int br = warp_n * (BN / 4) + ((lane >> 4) << 3) + (lane & 7);
        const int bc = ((lane >> 3) & 1) * 8;
        baddr[0] = cvta_smem(&sm.B[0][br][bc]);
        baddr[1] = cvta_smem(&sm.B[1][br][bc]);
    }

    uint4 ra[2][2], rb[2][BN / 64];
    ra[0][0] = *(const uint4*)(aghi);  ra[0][1] = *(const uint4*)(aghi + 8);
    ra[1][0] = *(const uint4*)(aglo);  ra[1][1] = *(const uint4*)(aglo + 8);
    if (BN == 128) {
        rb[0][0] = *(const uint4*)(bghi);  rb[0][BN/64 - 1] = *(const uint4*)(bghi + 8);
        rb[1][0] = *(const uint4*)(bglo);  rb[1][BN/64 - 1] = *(const uint4*)(bglo + 8);
    } else {
        rb[0][0] = *(const uint4*)(bghi);
        rb[1][0] = *(const uint4*)(bglo);
    }

    for (int ch = 0; ch < NCH; ch++) {
        __syncthreads();
        *(uint4*)&sm.A[0][arow][acol]     = ra[0][0];
        *(uint4*)&sm.A[0][arow][acol + 8] = ra[0][1];
        *(uint4*)&sm.A[1][arow][acol]     = ra[1][0];
        *(uint4*)&sm.A[1][arow][acol + 8] = ra[1][1];
        if (BN == 128) {
            *(uint4*)&sm.B[0][brow][bcol]     = rb[0][0];
            *(uint4*)&sm.B[0][brow][bcol + 8] = rb[0][BN/64 - 1];
            *(uint4*)&sm.B[1][brow][bcol]     = rb[1][0];
            *(uint4*)&sm.B[1][brow][bcol + 8] = rb[1][BN/64 - 1];
        } else {
            *(uint4*)&sm.B[0][brow][bcol] = rb[0][0];
            *(uint4*)&sm.B[1][brow][bcol] = rb[1][0];
        }
        __syncthreads();

        if (ch + 1 < NCH) {
            aghi += 32; aglo += 32; bghi += 32; bglo += 32;
            ra[0][0] = *(const uint4*)(aghi);  ra[0][1] = *(const uint4*)(aghi + 8);
            ra[1][0] = *(const uint4*)(aglo);  ra[1][1] = *(const uint4*)(aglo + 8);
            if (BN == 128) {
                rb[0][0] = *(const uint4*)(bghi);  rb[0][BN/64 - 1] = *(const uint4*)(bghi + 8);
                rb[1][0] = *(const uint4*)(bglo);  rb[1][BN/64 - 1] = *(const uint4*)(bglo + 8);
            } else {
                rb[0][0] = *(const uint4*)(bghi);
                rb[1][0] = *(const uint4*)(bglo);
            }
        }

#pragma unroll
        for (int kk = 0; kk < 2; kk++) {
            uint32_t bh[2 * NF], bl[2 * NF];
            ldmx4(bh, baddr[0] + kk * 32);
            ldmx4(bl, baddr[1] + kk * 32);
            if (NF == 4) {
                ldmx4(bh + 4, baddr[0] + 1280 + kk * 32);
                ldmx4(bl + 4, baddr[1] + 1280 + kk * 32);
            }
#pragma unroll
            for (int mf = 0; mf < 4; mf++) {
                uint32_t ah[4], al[4];
                ldmx4(ah, aaddr[0] + (uint32_t)(mf * 1280) + kk * 32);
                ldmx4(al, aaddr[1] + (uint32_t)(mf * 1280) + kk * 32);
#pragma unroll
                for (int nf = 0; nf < NF; nf++) {
                    mma16816(acc[mf][nf], ah, bh[2 * nf], bh[2 * nf + 1]);
                    mma16816(acc[mf][nf], ah, bl[2 * nf], bl[2 * nf + 1]);
                    mma16816(acc[mf][nf], al, bh[2 * nf], bh[2 * nf + 1]);
                }
            }
        }
    }
}

// ---------------- kernel 0: zero output + counts ----------------
__global__ void zero_kernel(float* __restrict__ y) {
    const int n = NTOK * TOUT;
    for (int i = blockIdx.x * blockDim.x + threadIdx.x; i < n;
         i += gridDim.x * blockDim.x)
        y[i] = 0.f;
    if (blockIdx.x == 0 && threadIdx.x < NEXP) g_cnt[threadIdx.x] = 0;
}

// ---------------- kernel 0b: split fp32 -> bf16 hi/lo, vectorized ----------------
__global__ void split_all_kernel(const float* __restrict__ x,  const float* __restrict__ W1,
                                 const float* __restrict__ W2, const float* __restrict__ Wm) {
    const int stride = gridDim.x * blockDim.x;
    const int t = blockIdx.x * blockDim.x + threadIdx.x;
#define SPLIT_LOOP(SRC, HI, LO, N)                                            \
    for (int i = t; i < (N) / 4; i += stride) {                               \
        const float4 v = ((const float4*)SRC)[i];                             \
        __nv_bfloat162 h01, h23, l01, l23;                                    \
        h01.x = __float2bfloat16_rn(v.x); h01.y = __float2bfloat16_rn(v.y);   \
        h23.x = __float2bfloat16_rn(v.z); h23.y = __float2bfloat16_rn(v.w);   \
        l01.x = __float2bfloat16_rn(v.x - __bfloat162float(h01.x));           \
        l01.y = __float2bfloat16_rn(v.y - __bfloat162float(h01.y));           \
        l23.x = __float2bfloat16_rn(v.z - __bfloat162float(h23.x));           \
        l23.y = __float2bfloat16_rn(v.w - __bfloat162float(h23.y));           \
        ((__nv_bfloat162*)HI)[2 * i]     = h01;                               \
        ((__nv_bfloat162*)HI)[2 * i + 1] = h23;                               \
        ((__nv_bfloat162*)LO)[2 * i]     = l01;                               \
        ((__nv_bfloat162*)LO)[2 * i + 1] = l23;                               \
    }
    SPLIT_LOOP(x,  g_xhi,  g_xlo,  NTOK * DIN)
    SPLIT_LOOP(W1, g_w1hi, g_w1lo, NEXP * HDIM * DIN)
    SPLIT_LOOP(W2, g_w2hi, g_w2lo, NEXP * CDIM * HDIM)
    SPLIT_LOOP(Wm, g_wmhi, g_wmlo, NEXP * TOUT * CDIM)
#undef SPLIT_LOOP
}

// ---------------- kernel 1: gating (one warp per token) ----------------
__global__ __launch_bounds__(256) void gate_kernel(const float* __restrict__ x,
                                                   const float* __restrict__ wg) {
    const int tok  = (blockIdx.x * blockDim.x + threadIdx.x) >> 5;
    const int lane = threadIdx.x & 31;
    if (tok >= NTOK) return;
    const float* xr = x + (size_t)tok * DIN;

    float acc[8];
#pragma unroll
    for (int e = 0; e < 8; e++) acc[e] = 0.f;

#pragma unroll
    for (int it = 0; it < DIN / 32; it++) {
        const int d = it * 32 + lane;
        const float xv = xr[d];
        const float4 w0 = *(const float4*)(wg + d * 8);
        const float4 w1 = *(const float4*)(wg + d * 8 + 4);
        acc[0] += xv * w0.x; acc[1] += xv * w0.y;
        acc[2] += xv * w0.z; acc[3] += xv * w0.w;
        acc[4] += xv * w1.x; acc[5] += xv * w1.y;
        acc[6] += xv * w1.z; acc[7] += xv * w1.w;
    }
#pragma unroll
    for (int e = 0; e < 8; e++)
#pragma unroll
        for (int off = 16; off; off >>= 1)
            acc[e] += __shfl_xor_sync(0xFFFFFFFFu, acc[e], off);

    if (lane == 0) {
        int i0 = 0; float v0 = acc[0];
#pragma unroll
        for (int e = 1; e < 8; e++) if (acc[e] > v0) { v0 = acc[e]; i0 = e; }
        int i1 = -1; float v1 = -3.4e38f;
#pragma unroll
        for (int e = 0; e < 8; e++)
            if (e != i0 && acc[e] > v1) { v1 = acc[e]; i1 = e; }
        const float tt = expf(v1 - v0);
        const float g0 = 1.f / (1.f + tt);
        const float g1 = tt / (1.f + tt);

        int s0 = atomicAdd(&g_cnt[i0], 1);
        g_tok[i0 * NTOK + s0]  = tok;
        g_gate[i0 * NTOK + s0] = g0;
        int s1 = atomicAdd(&g_cnt[i1], 1);
        g_tok[i1 * NTOK + s1]  = tok;
        g_gate[i1 * NTOK + s1] = g1;
    }
}

// ---------------- kernel 2: fc1 (split-bf16 tensor GEMM, BN=128) ----------------
// H[s,n] = relu( x[tok(s),:] . W1[e,n,:] + b1[e,n] ), stored as bf16 hi/lo
__global__ __launch_bounds__(256) void fc1_mma(const float* __restrict__ b1) {
    const int e   = blockIdx.z;
    const int cnt = g_cnt[e];
    const int m0  = blockIdx.x * 128;
    if (m0 >= cnt) return;
    const int n0  = blockIdx.y * 128;
    const int tid = threadIdx.x;

    __shared__ SmemT<128> sm;

    const int arow = tid >> 1;
    int r = m0 + arow; if (r >= cnt) r = cnt - 1;
    const int tok = g_tok[e * NTOK + r];
    const __nv_bfloat16* aghi = g_xhi + (size_t)tok * DIN + (tid & 1) * 16;
    const __nv_bfloat16* aglo = g_xlo + (size_t)tok * DIN + (tid & 1) * 16;
    const int brow = tid >> 1;
    const __nv_bfloat16* bghi = g_w1hi + ((size_t)e * HDIM + n0 + brow) * DIN + (tid & 1) * 16;
    const __nv_bfloat16* bglo = g_w1lo + ((size_t)e * HDIM + n0 + brow) * DIN + (tid & 1) * 16;

    float acc[4][4][4] = {};
    run_mainloop<DIN / 32, 128>(sm, aghi, aglo, bghi, bglo, acc);

    const int lane = tid & 31, wid = tid >> 5;
    const int warp_m = wid & 1, warp_n = wid >> 1;
#pragma unroll
    for (int nf = 0; nf < 4; nf++) {
        const int n = n0 + warp_n * 32 + nf * 8 + 2 * (lane & 3);
        const float bb0 = b1[e * HDIM + n];
        const float bb1 = b1[e * HDIM + n + 1];
#pragma unroll
        for (int mf = 0; mf < 4; mf++)
#pragma unroll
            for (int hr = 0; hr < 2; hr++) {
                const int m = m0 + warp_m * 64 + mf * 16 + (lane >> 2) + hr * 8;
                if (m < cnt) {
                    const float h0 = fmaxf(acc[mf][nf][2 * hr + 0] + bb0, 0.f);
                    const float h1 = fmaxf(acc[mf][nf][2 * hr + 1] + bb1, 0.f);
                    split_store2(g_Hhi, g_Hlo, ((size_t)e * NTOK + m) * HDIM + n, h0, h1);
                }
            }
    }
}

// ---------------- kernel 3: fc2 (split-bf16 tensor GEMM + gate, BN=64) ----------------
// O[s,c] = gate(s) * ( H[s,:] . W2[e,c,:] + b2[e,c] ), stored as bf16 hi/lo
__global__ __launch_bounds__(256) void fc2_mma(const float* __restrict__ b2) {
    const int e   = blockIdx.z;
    const int cnt = g_cnt[e];
    const int m0  = blockIdx.x * 128;
    if (m0 >= cnt) return;
    const int tid = threadIdx.x;

    __shared__ SmemT<64> sm;

    const int arow = tid >> 1;
    const __nv_bfloat16* aghi = g_Hhi + ((size_t)e * NTOK + m0 + arow) * HDIM + (tid & 1) * 16;
    const __nv_bfloat16* aglo = g_Hlo + ((size_t)e * NTOK + m0 + arow) * HDIM + (tid & 1) * 16;
    const int brow = tid >> 2;
    const __nv_bfloat16* bghi = g_w2hi + ((size_t)e * CDIM + brow) * HDIM + (tid & 3) * 8;
    const __nv_bfloat16* bglo = g_w2lo + ((size_t)e * CDIM + brow) * HDIM + (tid & 3) * 8;

    float acc[4][2][4] = {};
    run_mainloop<HDIM / 32, 64>(sm, aghi, aglo, bghi, bglo, acc);

    const int lane = tid & 31, wid = tid >> 5;
    const int warp_m = wid & 1, warp_n = wid >> 1;
#pragma unroll
    for (int nf = 0; nf < 2; nf++) {
        const int n = warp_n * 16 + nf * 8 + 2 * (lane & 3);
        const float bb0 = b2[e * CDIM + n];
        const float bb1 = b2[e * CDIM + n + 1];
#pragma unroll
        for (int mf = 0; mf < 4; mf++)
#pragma unroll
            for (int hr = 0; hr < 2; hr++) {
                const int m = m0 + warp_m * 64 + mf * 16 + (lane >> 2) + hr * 8;
                if (m < cnt) {
                    const float g = g_gate[e * NTOK + m];
                    const float o0 = (acc[mf][nf][2 * hr + 0] + bb0) * g;
                    const float o1 = (acc[mf][nf][2 * hr + 1] + bb1) * g;
                    split_store2(g_Ohi, g_Olo, ((size_t)e * NTOK + m) * CDIM + n, o0, o1);
                }
            }
    }
}

// ---------------- kernel 4: combine (split-bf16 tensor GEMM + atomic scatter, BN=128) ----------------
// y[tok(s), t] += O[s,:] . Wm[e,t,:]
__global__ __launch_bounds__(256) void combine_mma(float* __restrict__ y) {
    const int e   = blockIdx.z;
    const int cnt = g_cnt[e];
    const int m0  = blockIdx.x * 128;
    if (m0 >= cnt) return;
    const int n0  = blockIdx.y * 128;
    const int tid = threadIdx.x;

    __shared__ SmemT<128> sm;

    const int arow = tid >> 1;
    const __nv_bfloat16* aghi = g_Ohi + ((size_t)e * NTOK + m0 + arow) * CDIM + (tid & 1) * 16;
    const __nv_bfloat16* aglo = g_Olo + ((size_t)e * NTOK + m0 + arow) * CDIM + (tid & 1) * 16;
    const int brow = tid >> 1;
    const __nv_bfloat16* bghi = g_wmhi + ((size_t)e * TOUT + n0 + brow) * CDIM + (tid & 1) * 16;
    const __nv_bfloat16* bglo = g_wmlo + ((size_t)e * TOUT + n0 + brow) * CDIM + (tid & 1) * 16;

    float acc[4][4][4] = {};
    run_mainloop<CDIM / 32, 128>(sm, aghi, aglo, bghi, bglo, acc);

    const int lane = tid & 31, wid = tid >> 5;
    const int warp_m = wid & 1, warp_n = wid >> 1;
#pragma unroll
    for (int mf = 0; mf < 4; mf++)
#pragma unroll
        for (int hr = 0; hr < 2; hr++) {
            const int m = m0 + warp_m * 64 + mf * 16 + (lane >> 2) + hr * 8;
            if (m < cnt) {
                const int tok = g_tok[e * NTOK + m];
                float* yr = y + (size_t)tok * TOUT;
#pragma unroll
                for (int nf = 0; nf < 4; nf++) {
                    const int n = n0 + warp_n * 32 + nf * 8 + 2 * (lane & 3);
                    atomicAdd(yr + n,     acc[mf][nf][2 * hr + 0]);
                    atomicAdd(yr + n + 1, acc[mf][nf][2 * hr + 1]);
                }
            }
        }
}

// ---------------- kernel 5: EPS fixup ----------------
__global__ void eps_kernel(float* __restrict__ y) {
    const int n = NTOK * TOUT;
    for (int i = blockIdx.x * blockDim.x + threadIdx.x; i < n;
         i += gridDim.x * blockDim.x) {
        const float v = y[i];
        if (v == 0.f) y[i] = EPSV;
    }
}

// ---------------- launch ----------------
extern "C" void kernel_launch(void* const* d_in, const int* in_sizes, int n_in,
                              void* d_out, int out_size) {
    const float* x  = (const float*)d_in[0];
    // d_in[1] = labels (int64) — unused by the reference computation
    const float* wg = (const float*)d_in[2];
    const float* W1 = (const float*)d_in[3];
    const float* b1 = (const float*)d_in[4];
    const float* W2 = (const float*)d_in[5];
    const float* b2 = (const float*)d_in[6];
    const float* Wm = (const float*)d_in[7];
    float* y = (float*)d_out;

    zero_kernel<<<256, 256>>>(y);
    split_all_kernel<<<2048, 256>>>(x, W1, W2, Wm);
    gate_kernel<<<NTOK / 8, 256>>>(x, wg);

    dim3 g1(NTOK / 128, HDIM / 128, NEXP);  // (64, 2, 8)
    fc1_mma<<<g1, 256>>>(b1);

    dim3 g2(NTOK / 128, 1, NEXP);           // (64, 1, 8)
    fc2_mma<<<g2, 256>>>(b2);

    dim3 g3(NTOK / 128, TOUT / 128, NEXP);  // (64, 4, 8)
    combine_mma<<<g3, 256>>>(y);

    eps_kernel<<<512, 256>>>(y);
}

// round 8
// speedup vs baseline: 2.0874x; 1.0816x over previous
#include <cuda_runtime.h>
#include <cuda_bf16.h>
#include <math.h>
#include <stdint.h>

#define NTOK 8192
#define DIN  768
#define HDIM 256
#define NEXP 8
#define CDIM 64
#define TOUT 512
#define EPSV 2.2204460492503131e-16f

// ---------------- static device scratch (allocation-free rule) ----------------
__device__ int   g_cnt[NEXP];
__device__ int   g_tok[NEXP * NTOK];
__device__ float g_gate[NEXP * NTOK];

__device__ __nv_bfloat16 g_xhi[NTOK * DIN],        g_xlo[NTOK * DIN];
__device__ __nv_bfloat16 g_w1hi[NEXP * HDIM * DIN], g_w1lo[NEXP * HDIM * DIN];
__device__ __nv_bfloat16 g_w2hi[NEXP * CDIM * HDIM], g_w2lo[NEXP * CDIM * HDIM];
__device__ __nv_bfloat16 g_wmhi[NEXP * TOUT * CDIM], g_wmlo[NEXP * TOUT * CDIM];
__device__ __nv_bfloat16 g_Hhi[(size_t)NEXP * NTOK * HDIM], g_Hlo[(size_t)NEXP * NTOK * HDIM];
__device__ __nv_bfloat16 g_Ohi[(size_t)NEXP * NTOK * CDIM], g_Olo[(size_t)NEXP * NTOK * CDIM];

// ---------------- helpers ----------------
__device__ __forceinline__ uint32_t smem_u32(const void* p) {
    return (uint32_t)__cvta_generic_to_shared(p);
}
__device__ __forceinline__ void ldmx4(uint32_t* r, uint32_t addr) {
    asm volatile("ldmatrix.sync.aligned.m8n8.x4.shared.b16 {%0,%1,%2,%3}, [%4];\n"
                 : "=r"(r[0]), "=r"(r[1]), "=r"(r[2]), "=r"(r[3]) : "r"(addr));
}
__device__ __forceinline__ void mma16816(float* c, const uint32_t* a, uint32_t b0, uint32_t b1) {
    asm volatile(
        "mma.sync.aligned.m16n8k16.row.col.f32.bf16.bf16.f32 "
        "{%0,%1,%2,%3}, {%4,%5,%6,%7}, {%8,%9}, {%0,%1,%2,%3};\n"
        : "+f"(c[0]), "+f"(c[1]), "+f"(c[2]), "+f"(c[3])
        : "r"(a[0]), "r"(a[1]), "r"(a[2]), "r"(a[3]), "r"(b0), "r"(b1));
}
__device__ __forceinline__ void cp16(uint32_t dst, const void* src) {
    asm volatile("cp.async.cg.shared.global [%0], [%1], 16;" :: "r"(dst), "l"(src));
}
#define CP_COMMIT() asm volatile("cp.async.commit_group;" ::: "memory")
#define CP_WAIT1()  asm volatile("cp.async.wait_group 1;" ::: "memory")
#define CP_WAIT0()  asm volatile("cp.async.wait_group 0;" ::: "memory")

__device__ __forceinline__ void split_store2(__nv_bfloat16* hi, __nv_bfloat16* lo,
                                             size_t off, float v0, float v1) {
    __nv_bfloat16 h0 = __float2bfloat16_rn(v0), h1 = __float2bfloat16_rn(v1);
    __nv_bfloat162 th; th.x = h0; th.y = h1;
    __nv_bfloat162 tl;
    tl.x = __float2bfloat16_rn(v0 - __bfloat162float(h0));
    tl.y = __float2bfloat16_rn(v1 - __bfloat162float(h1));
    *(__nv_bfloat162*)(hi + off) = th;
    *(__nv_bfloat162*)(lo + off) = tl;
}

// ---------------- smem geometry ----------------
// Stage layout (bytes): Ahi[128x40] @0, Alo @ASZ, Bhi @2*ASZ, Blo @2*ASZ+BSZ.
// Row pitch 80 B (40 bf16) keeps ldmatrix conflict-free; 80 is 16B-aligned.
#define ASZ 10240
#define BSZ(BN) ((BN) * 80)
#define STGSZ(BN) (2 * ASZ + 2 * BSZ(BN))
#define SMEM_128 (2 * STGSZ(128))   // 81920
#define SMEM_64  (2 * STGSZ(64))    // 61440

// ---------------- shared mainloop (cp.async double-buffered) ----------------
// Block tile 128M x BN x 32K. Warp grid 2(M) x 4(N); per-warp tile 64 x (BN/4).
// Gmem pointers pre-offset to (row, this thread's k-seg); advance 32/chunk.
template <int NCH, int BN>
__device__ __forceinline__ void run_mainloop_cp(
    uint32_t sb,
    const __nv_bfloat16* aghi, const __nv_bfloat16* aglo,
    const __nv_bfloat16* bghi, const __nv_bfloat16* bglo,
    float (&acc)[4][BN / 32][4])
{
    constexpr int NF = BN / 32;
    constexpr int BS = BSZ(BN);
    constexpr int ST = STGSZ(BN);
    const int tid  = threadIdx.x;
    const int lane = tid & 31;
    const int wid  = tid >> 5;
    const int warp_m = wid & 1;
    const int warp_n = wid >> 1;

    // producer smem offsets
    const uint32_t a_off = (tid >> 1) * 80 + (tid & 1) * 32;
    const uint32_t b_off = (BN == 128) ? ((tid >> 1) * 80 + (tid & 1) * 32)
                                       : ((tid >> 2) * 80 + (tid & 3) * 16);

    // consumer (ldmatrix) base addresses, stage 0
    const int ar = warp_m * 64 + ((lane >> 3) & 1) * 8 + (lane & 7);
    const int ac = (lane >> 4) * 8;
    const uint32_t la = sb + ar * 80 + ac * 2;
    const int br = warp_n * (BN / 4) + ((lane >> 4) << 3) + (lane & 7);
    const int bc = ((lane >> 3) & 1) * 8;
    const uint32_t lb = sb + 2 * ASZ + br * 80 + bc * 2;

    auto load_stage = [&](int s) {
        const uint32_t st = sb + s * ST;
        cp16(st + a_off,            aghi);
        cp16(st + a_off + 16,       aghi + 8);
        cp16(st + ASZ + a_off,      aglo);
        cp16(st + ASZ + a_off + 16, aglo + 8);
        if (BN == 128) {
            cp16(st + 2 * ASZ + b_off,           bghi);
            cp16(st + 2 * ASZ + b_off + 16,      bghi + 8);
            cp16(st + 2 * ASZ + BS + b_off,      bglo);
            cp16(st + 2 * ASZ + BS + b_off + 16, bglo + 8);
        } else {
            cp16(st + 2 * ASZ + b_off,      bghi);
            cp16(st + 2 * ASZ + BS + b_off, bglo);
        }
        aghi += 32; aglo += 32; bghi += 32; bglo += 32;
    };

    load_stage(0);
    CP_COMMIT();

    for (int ch = 0; ch < NCH; ch++) {
        if (ch + 1 < NCH) {
            load_stage((ch + 1) & 1);
            CP_COMMIT();
            CP_WAIT1();
        } else {
            CP_WAIT0();
        }
        __syncthreads();

        const uint32_t sa  = la + (ch & 1) * ST;
        const uint32_t sbb = lb + (ch & 1) * ST;
#pragma unroll
        for (int kk = 0; kk < 2; kk++) {
            uint32_t bh[2 * NF], bl[2 * NF];
            ldmx4(bh, sbb + kk * 32);
            ldmx4(bl, sbb + BS + kk * 32);
            if (NF == 4) {
                ldmx4(bh + 4, sbb + 1280 + kk * 32);
                ldmx4(bl + 4, sbb + BS + 1280 + kk * 32);
            }
#pragma unroll
            for (int mf = 0; mf < 4; mf++) {
                uint32_t ah[4], al[4];
                ldmx4(ah, sa + (uint32_t)(mf * 1280) + kk * 32);
                ldmx4(al, sa + ASZ + (uint32_t)(mf * 1280) + kk * 32);
#pragma unroll
                for (int nf = 0; nf < NF; nf++) {
                    mma16816(acc[mf][nf], ah, bh[2 * nf], bh[2 * nf + 1]);
                    mma16816(acc[mf][nf], ah, bl[2 * nf], bl[2 * nf + 1]);
                    mma16816(acc[mf][nf], al, bh[2 * nf], bh[2 * nf + 1]);
                }
            }
        }
        __syncthreads();
    }
}

// ---------------- kernel 0: zero output + counts ----------------
__global__ void zero_kernel(float* __restrict__ y) {
    const int n = NTOK * TOUT;
    for (int i = blockIdx.x * blockDim.x + threadIdx.x; i < n;
         i += gridDim.x * blockDim.x)
        y[i] = 0.f;
    if (blockIdx.x == 0 && threadIdx.x < NEXP) g_cnt[threadIdx.x] = 0;
}

// ---------------- kernel 0b: split fp32 -> bf16 hi/lo, vectorized ----------------
__global__ void split_all_kernel(const float* __restrict__ x,  const float* __restrict__ W1,
                                 const float* __restrict__ W2, const float* __restrict__ Wm) {
    const int stride = gridDim.x * blockDim.x;
    const int t = blockIdx.x * blockDim.x + threadIdx.x;
#define SPLIT_LOOP(SRC, HI, LO, N)                                            \
    for (int i = t; i < (N) / 4; i += stride) {                               \
        const float4 v = ((const float4*)SRC)[i];                             \
        __nv_bfloat162 h01, h23, l01, l23;                                    \
        h01.x = __float2bfloat16_rn(v.x); h01.y = __float2bfloat16_rn(v.y);   \
        h23.x = __float2bfloat16_rn(v.z); h23.y = __float2bfloat16_rn(v.w);   \
        l01.x = __float2bfloat16_rn(v.x - __bfloat162float(h01.x));           \
        l01.y = __float2bfloat16_rn(v.y - __bfloat162float(h01.y));           \
        l23.x = __float2bfloat16_rn(v.z - __bfloat162float(h23.x));           \
        l23.y = __float2bfloat16_rn(v.w - __bfloat162float(h23.y));           \
        ((__nv_bfloat162*)HI)[2 * i]     = h01;                               \
        ((__nv_bfloat162*)HI)[2 * i + 1] = h23;                               \
        ((__nv_bfloat162*)LO)[2 * i]     = l01;                               \
        ((__nv_bfloat162*)LO)[2 * i + 1] = l23;                               \
    }
    SPLIT_LOOP(x,  g_xhi,  g_xlo,  NTOK * DIN)
    SPLIT_LOOP(W1, g_w1hi, g_w1lo, NEXP * HDIM * DIN)
    SPLIT_LOOP(W2, g_w2hi, g_w2lo, NEXP * CDIM * HDIM)
    SPLIT_LOOP(Wm, g_wmhi, g_wmlo, NEXP * TOUT * CDIM)
#undef SPLIT_LOOP
}

// ---------------- kernel 1: gating (one warp per token) ----------------
__global__ __launch_bounds__(256) void gate_kernel(const float* __restrict__ x,
                                                   const float* __restrict__ wg) {
    const int tok  = (blockIdx.x * blockDim.x + threadIdx.x) >> 5;
    const int lane = threadIdx.x & 31;
    if (tok >= NTOK) return;
    const float* xr = x + (size_t)tok * DIN;

    float acc[8];
#pragma unroll
    for (int e = 0; e < 8; e++) acc[e] = 0.f;

#pragma unroll
    for (int it = 0; it < DIN / 32; it++) {
        const int d = it * 32 + lane;
        const float xv = xr[d];
        const float4 w0 = *(const float4*)(wg + d * 8);
        const float4 w1 = *(const float4*)(wg + d * 8 + 4);
        acc[0] += xv * w0.x; acc[1] += xv * w0.y;
        acc[2] += xv * w0.z; acc[3] += xv * w0.w;
        acc[4] += xv * w1.x; acc[5] += xv * w1.y;
        acc[6] += xv * w1.z; acc[7] += xv * w1.w;
    }
#pragma unroll
    for (int e = 0; e < 8; e++)
#pragma unroll
        for (int off = 16; off; off >>= 1)
            acc[e] += __shfl_xor_sync(0xFFFFFFFFu, acc[e], off);

    if (lane == 0) {
        int i0 = 0; float v0 = acc[0];
#pragma unroll
        for (int e = 1; e < 8; e++) if (acc[e] > v0) { v0 = acc[e]; i0 = e; }
        int i1 = -1; float v1 = -3.4e38f;
#pragma unroll
        for (int e = 0; e < 8; e++)
            if (e != i0 && acc[e] > v1) { v1 = acc[e]; i1 = e; }
        const float tt = expf(v1 - v0);
        const float g0 = 1.f / (1.f + tt);
        const float g1 = tt / (1.f + tt);

        int s0 = atomicAdd(&g_cnt[i0], 1);
        g_tok[i0 * NTOK + s0]  = tok;
        g_gate[i0 * NTOK + s0] = g0;
        int s1 = atomicAdd(&g_cnt[i1], 1);
        g_tok[i1 * NTOK + s1]  = tok;
        g_gate[i1 * NTOK + s1] = g1;
    }
}

// ---------------- kernel 2: fc1 (split-bf16 mma, BN=128, cp.async) ----------------
__global__ __launch_bounds__(256, 2) void fc1_mma(const float* __restrict__ b1) {
    const int e   = blockIdx.z;
    const int cnt = g_cnt[e];
    const int m0  = blockIdx.x * 128;
    if (m0 >= cnt) return;
    const int n0  = blockIdx.y * 128;
    const int tid = threadIdx.x;

    extern __shared__ char dsm[];
    const uint32_t sb = smem_u32(dsm);

    const int arow = tid >> 1;
    int r = m0 + arow; if (r >= cnt) r = cnt - 1;
    const int tok = g_tok[e * NTOK + r];
    const __nv_bfloat16* aghi = g_xhi + (size_t)tok * DIN + (tid & 1) * 16;
    const __nv_bfloat16* aglo = g_xlo + (size_t)tok * DIN + (tid & 1) * 16;
    const int brow = tid >> 1;
    const __nv_bfloat16* bghi = g_w1hi + ((size_t)e * HDIM + n0 + brow) * DIN + (tid & 1) * 16;
    const __nv_bfloat16* bglo = g_w1lo + ((size_t)e * HDIM + n0 + brow) * DIN + (tid & 1) * 16;

    float acc[4][4][4] = {};
    run_mainloop_cp<DIN / 32, 128>(sb, aghi, aglo, bghi, bglo, acc);

    const int lane = tid & 31, wid = tid >> 5;
    const int warp_m = wid & 1, warp_n = wid >> 1;
#pragma unroll
    for (int nf = 0; nf < 4; nf++) {
        const int n = n0 + warp_n * 32 + nf * 8 + 2 * (lane & 3);
        const float bb0 = b1[e * HDIM + n];
        const float bb1 = b1[e * HDIM + n + 1];
#pragma unroll
        for (int mf = 0; mf < 4; mf++)
#pragma unroll
            for (int hr = 0; hr < 2; hr++) {
                const int m = m0 + warp_m * 64 + mf * 16 + (lane >> 2) + hr * 8;
                if (m < cnt) {
                    const float h0 = fmaxf(acc[mf][nf][2 * hr + 0] + bb0, 0.f);
                    const float h1 = fmaxf(acc[mf][nf][2 * hr + 1] + bb1, 0.f);
                    split_store2(g_Hhi, g_Hlo, ((size_t)e * NTOK + m) * HDIM + n, h0, h1);
                }
            }
    }
}

// ---------------- kernel 3: fc2 (split-bf16 mma + gate, BN=64, cp.async) ----------------
__global__ __launch_bounds__(256, 2) void fc2_mma(const float* __restrict__ b2) {
    const int e   = blockIdx.z;
    const int cnt = g_cnt[e];
    const int m0  = blockIdx.x * 128;
    if (m0 >= cnt) return;
    const int tid = threadIdx.x;

    extern __shared__ char dsm[];
    const uint32_t sb = smem_u32(dsm);

    const int arow = tid >> 1;
    const __nv_bfloat16* aghi = g_Hhi + ((size_t)e * NTOK + m0 + arow) * HDIM + (tid & 1) * 16;
    const __nv_bfloat16* aglo = g_Hlo + ((size_t)e * NTOK + m0 + arow) * HDIM + (tid & 1) * 16;
    const int brow = tid >> 2;
    const __nv_bfloat16* bghi = g_w2hi + ((size_t)e * CDIM + brow) * HDIM + (tid & 3) * 8;
    const __nv_bfloat16* bglo = g_w2lo + ((size_t)e * CDIM + brow) * HDIM + (tid & 3) * 8;

    float acc[4][2][4] = {};
    run_mainloop_cp<HDIM / 32, 64>(sb, aghi, aglo, bghi, bglo, acc);

    const int lane = tid & 31, wid = tid >> 5;
    const int warp_m = wid & 1, warp_n = wid >> 1;
#pragma unroll
    for (int nf = 0; nf < 2; nf++) {
        const int n = warp_n * 16 + nf * 8 + 2 * (lane & 3);
        const float bb0 = b2[e * CDIM + n];
        const float bb1 = b2[e * CDIM + n + 1];
#pragma unroll
        for (int mf = 0; mf < 4; mf++)
#pragma unroll
            for (int hr = 0; hr < 2; hr++) {
                const int m = m0 + warp_m * 64 + mf * 16 + (lane >> 2) + hr * 8;
                if (m < cnt) {
                    const float g = g_gate[e * NTOK + m];
                    const float o0 = (acc[mf][nf][2 * hr + 0] + bb0) * g;
                    const float o1 = (acc[mf][nf][2 * hr + 1] + bb1) * g;
                    split_store2(g_Ohi, g_Olo, ((size_t)e * NTOK + m) * CDIM + n, o0, o1);
                }
            }
    }
}

// ---------------- kernel 4: combine (split-bf16 mma + atomic scatter, BN=128, cp.async) ----------------
__global__ __launch_bounds__(256, 2) void combine_mma(float* __restrict__ y) {
    const int e   = blockIdx.z;
    const int cnt = g_cnt[e];
    const int m0  = blockIdx.x * 128;
    if (m0 >= cnt) return;
    const int n0  = blockIdx.y * 128;
    const int tid = threadIdx.x;

    extern __shared__ char dsm[];
    const uint32_t sb = smem_u32(dsm);

    const int arow = tid >> 1;
    const __nv_bfloat16* aghi = g_Ohi + ((size_t)e * NTOK + m0 + arow) * CDIM + (tid & 1) * 16;
    const __nv_bfloat16* aglo = g_Olo + ((size_t)e * NTOK + m0 + arow) * CDIM + (tid & 1) * 16;
    const int brow = tid >> 1;
    const __nv_bfloat16* bghi = g_wmhi + ((size_t)e * TOUT + n0 + brow) * CDIM + (tid & 1) * 16;
    const __nv_bfloat16* bglo = g_wmlo + ((size_t)e * TOUT + n0 + brow) * CDIM + (tid & 1) * 16;

    float acc[4][4][4] = {};
    run_mainloop_cp<CDIM / 32, 128>(sb, aghi, aglo, bghi, bglo, acc);

    const int lane = tid & 31, wid = tid >> 5;
    const int warp_m = wid & 1, warp_n = wid >> 1;
#pragma unroll
    for (int mf = 0; mf < 4; mf++)
#pragma unroll
        for (int hr = 0; hr < 2; hr++) {
            const int m = m0 + warp_m * 64 + mf * 16 + (lane >> 2) + hr * 8;
            if (m < cnt) {
                const int tok = g_tok[e * NTOK + m];
                float* yr = y + (size_t)tok * TOUT;
#pragma unroll
                for (int nf = 0; nf < 4; nf++) {
                    const int n = n0 + warp_n * 32 + nf * 8 + 2 * (lane & 3);
                    atomicAdd(yr + n,     acc[mf][nf][2 * hr + 0]);
                    atomicAdd(yr + n + 1, acc[mf][nf][2 * hr + 1]);
                }
            }
        }
}

// ---------------- kernel 5: EPS fixup ----------------
__global__ void eps_kernel(float* __restrict__ y) {
    const int n = NTOK * TOUT;
    for (int i = blockIdx.x * blockDim.x + threadIdx.x; i < n;
         i += gridDim.x * blockDim.x) {
        const float v = y[i];
        if (v == 0.f) y[i] = EPSV;
    }
}

// ---------------- launch ----------------
extern "C" void kernel_launch(void* const* d_in, const int* in_sizes, int n_in,
                              void* d_out, int out_size) {
    const float* x  = (const float*)d_in[0];
    // d_in[1] = labels (int64) — unused by the reference computation
    const float* wg = (const float*)d_in[2];
    const float* W1 = (const float*)d_in[3];
    const float* b1 = (const float*)d_in[4];
    const float* W2 = (const float*)d_in[5];
    const float* b2 = (const float*)d_in[6];
    const float* Wm = (const float*)d_in[7];
    float* y = (float*)d_out;

    cudaFuncSetAttribute(fc1_mma,     cudaFuncAttributeMaxDynamicSharedMemorySize, SMEM_128);
    cudaFuncSetAttribute(fc2_mma,     cudaFuncAttributeMaxDynamicSharedMemorySize, SMEM_64);
    cudaFuncSetAttribute(combine_mma, cudaFuncAttributeMaxDynamicSharedMemorySize, SMEM_128);

    zero_kernel<<<256, 256>>>(y);
    split_all_kernel<<<2048, 256>>>(x, W1, W2, Wm);
    gate_kernel<<<NTOK / 8, 256>>>(x, wg);

    dim3 g1(NTOK / 128, HDIM / 128, NEXP);  // (64, 2, 8)
    fc1_mma<<<g1, 256, SMEM_128>>>(b1);

    dim3 g2(NTOK / 128, 1, NEXP);           // (64, 1, 8)
    fc2_mma<<<g2, 256, SMEM_64>>>(b2);

    dim3 g3(NTOK / 128, TOUT / 128, NEXP);  // (64, 4, 8)
    combine_mma<<<g3, 256, SMEM_128>>>(y);

    eps_kernel<<<512, 256>>>(y);
}

// round 9
// speedup vs baseline: 2.1406x; 1.0255x over previous
#include <cuda_runtime.h>
#include <cuda_bf16.h>
#include <math.h>
#include <stdint.h>

#define NTOK 8192
#define DIN  768
#define HDIM 256
#define NEXP 8
#define CDIM 64
#define TOUT 512
#define EPSV 2.2204460492503131e-16f

// ---------------- static device scratch (allocation-free rule) ----------------
__device__ int   g_cnt[NEXP];
__device__ int   g_tok[NEXP * NTOK];
__device__ float g_gate[NEXP * NTOK];

__device__ __nv_bfloat16 g_xhi[NTOK * DIN],        g_xlo[NTOK * DIN];
__device__ __nv_bfloat16 g_w1hi[NEXP * HDIM * DIN], g_w1lo[NEXP * HDIM * DIN];
__device__ __nv_bfloat16 g_w2hi[NEXP * CDIM * HDIM], g_w2lo[NEXP * CDIM * HDIM];
__device__ __nv_bfloat16 g_wmhi[NEXP * TOUT * CDIM], g_wmlo[NEXP * TOUT * CDIM];
__device__ __nv_bfloat16 g_Hhi[(size_t)NEXP * NTOK * HDIM], g_Hlo[(size_t)NEXP * NTOK * HDIM];
__device__ __nv_bfloat16 g_Ohi[(size_t)NEXP * NTOK * CDIM], g_Olo[(size_t)NEXP * NTOK * CDIM];

// ---------------- helpers ----------------
__device__ __forceinline__ uint32_t smem_u32(const void* p) {
    return (uint32_t)__cvta_generic_to_shared(p);
}
__device__ __forceinline__ void ldmx4(uint32_t* r, uint32_t addr) {
    asm volatile("ldmatrix.sync.aligned.m8n8.x4.shared.b16 {%0,%1,%2,%3}, [%4];\n"
                 : "=r"(r[0]), "=r"(r[1]), "=r"(r[2]), "=r"(r[3]) : "r"(addr));
}
__device__ __forceinline__ void mma16816(float* c, const uint32_t* a, uint32_t b0, uint32_t b1) {
    asm volatile(
        "mma.sync.aligned.m16n8k16.row.col.f32.bf16.bf16.f32 "
        "{%0,%1,%2,%3}, {%4,%5,%6,%7}, {%8,%9}, {%0,%1,%2,%3};\n"
        : "+f"(c[0]), "+f"(c[1]), "+f"(c[2]), "+f"(c[3])
        : "r"(a[0]), "r"(a[1]), "r"(a[2]), "r"(a[3]), "r"(b0), "r"(b1));
}
__device__ __forceinline__ void cp16(uint32_t dst, const void* src) {
    asm volatile("cp.async.cg.shared.global [%0], [%1], 16;" :: "r"(dst), "l"(src));
}
#define CP_COMMIT() asm volatile("cp.async.commit_group;" ::: "memory")
#define CP_WAIT1()  asm volatile("cp.async.wait_group 1;" ::: "memory")
#define CP_WAIT0()  asm volatile("cp.async.wait_group 0;" ::: "memory")

__device__ __forceinline__ void split_store2(__nv_bfloat16* hi, __nv_bfloat16* lo,
                                             size_t off, float v0, float v1) {
    __nv_bfloat16 h0 = __float2bfloat16_rn(v0), h1 = __float2bfloat16_rn(v1);
    __nv_bfloat162 th; th.x = h0; th.y = h1;
    __nv_bfloat162 tl;
    tl.x = __float2bfloat16_rn(v0 - __bfloat162float(h0));
    tl.y = __float2bfloat16_rn(v1 - __bfloat162float(h1));
    *(__nv_bfloat162*)(hi + off) = th;
    *(__nv_bfloat162*)(lo + off) = tl;
}

// ---------------- smem geometry ----------------
// Stage layout (bytes): Ahi[128x40] @0, Alo @ASZ, Bhi @2*ASZ, Blo @2*ASZ+BSZ.
// Row pitch 80 B (40 bf16) keeps ldmatrix conflict-free; 80 is 16B-aligned.
#define ASZ 10240
#define BSZ(BN) ((BN) * 80)
#define STGSZ(BN) (2 * ASZ + 2 * BSZ(BN))
#define SMEM_128 (2 * STGSZ(128))   // 81920
#define SMEM_64  (2 * STGSZ(64))    // 61440

// ---------------- shared mainloop (cp.async double-buffered) ----------------
// Block tile 128M x BN x 32K. Warp grid 2(M) x 4(N); per-warp tile 64 x (BN/4).
// Gmem pointers pre-offset to (row, this thread's k-seg); advance 32/chunk.
// MMA issue order: per A-fragment, hh across all nf, then hl, then lh — each
// accumulator still sees hh->hl->lh (bitwise-identical), but dependent MMAs
// on the same C registers are NF apart instead of adjacent.
template <int NCH, int BN>
__device__ __forceinline__ void run_mainloop_cp(
    uint32_t sb,
    const __nv_bfloat16* aghi, const __nv_bfloat16* aglo,
    const __nv_bfloat16* bghi, const __nv_bfloat16* bglo,
    float (&acc)[4][BN / 32][4])
{
    constexpr int NF = BN / 32;
    constexpr int BS = BSZ(BN);
    constexpr int ST = STGSZ(BN);
    const int tid  = threadIdx.x;
    const int lane = tid & 31;
    const int wid  = tid >> 5;
    const int warp_m = wid & 1;
    const int warp_n = wid >> 1;

    // producer smem offsets
    const uint32_t a_off = (tid >> 1) * 80 + (tid & 1) * 32;
    const uint32_t b_off = (BN == 128) ? ((tid >> 1) * 80 + (tid & 1) * 32)
                                       : ((tid >> 2) * 80 + (tid & 3) * 16);

    // consumer (ldmatrix) base addresses, stage 0
    const int ar = warp_m * 64 + ((lane >> 3) & 1) * 8 + (lane & 7);
    const int ac = (lane >> 4) * 8;
    const uint32_t la = sb + ar * 80 + ac * 2;
    const int br = warp_n * (BN / 4) + ((lane >> 4) << 3) + (lane & 7);
    const int bc = ((lane >> 3) & 1) * 8;
    const uint32_t lb = sb + 2 * ASZ + br * 80 + bc * 2;

    auto load_stage = [&](int s) {
        const uint32_t st = sb + s * ST;
        cp16(st + a_off,            aghi);
        cp16(st + a_off + 16,       aghi + 8);
        cp16(st + ASZ + a_off,      aglo);
        cp16(st + ASZ + a_off + 16, aglo + 8);
        if (BN == 128) {
            cp16(st + 2 * ASZ + b_off,           bghi);
            cp16(st + 2 * ASZ + b_off + 16,      bghi + 8);
            cp16(st + 2 * ASZ + BS + b_off,      bglo);
            cp16(st + 2 * ASZ + BS + b_off + 16, bglo + 8);
        } else {
            cp16(st + 2 * ASZ + b_off,      bghi);
            cp16(st + 2 * ASZ + BS + b_off, bglo);
        }
        aghi += 32; aglo += 32; bghi += 32; bglo += 32;
    };

    load_stage(0);
    CP_COMMIT();

    for (int ch = 0; ch < NCH; ch++) {
        if (ch + 1 < NCH) {
            load_stage((ch + 1) & 1);
            CP_COMMIT();
            CP_WAIT1();
        } else {
            CP_WAIT0();
        }
        __syncthreads();

        const uint32_t sa  = la + (ch & 1) * ST;
        const uint32_t sbb = lb + (ch & 1) * ST;
#pragma unroll
        for (int kk = 0; kk < 2; kk++) {
            uint32_t bh[2 * NF], bl[2 * NF];
            ldmx4(bh, sbb + kk * 32);
            ldmx4(bl, sbb + BS + kk * 32);
            if (NF == 4) {
                ldmx4(bh + 4, sbb + 1280 + kk * 32);
                ldmx4(bl + 4, sbb + BS + 1280 + kk * 32);
            }
#pragma unroll
            for (int mf = 0; mf < 4; mf++) {
                uint32_t ah[4], al[4];
                ldmx4(ah, sa + (uint32_t)(mf * 1280) + kk * 32);
                ldmx4(al, sa + ASZ + (uint32_t)(mf * 1280) + kk * 32);
#pragma unroll
                for (int nf = 0; nf < NF; nf++)
                    mma16816(acc[mf][nf], ah, bh[2 * nf], bh[2 * nf + 1]);
#pragma unroll
                for (int nf = 0; nf < NF; nf++)
                    mma16816(acc[mf][nf], ah, bl[2 * nf], bl[2 * nf + 1]);
#pragma unroll
                for (int nf = 0; nf < NF; nf++)
                    mma16816(acc[mf][nf], al, bh[2 * nf], bh[2 * nf + 1]);
            }
        }
        __syncthreads();
    }
}

// ---------------- kernel 0: zero output + counts (vectorized) ----------------
__global__ void zero_kernel(float4* __restrict__ y) {
    const int n = NTOK * TOUT / 4;
    const float4 z = {0.f, 0.f, 0.f, 0.f};
    for (int i = blockIdx.x * blockDim.x + threadIdx.x; i < n;
         i += gridDim.x * blockDim.x)
        y[i] = z;
    if (blockIdx.x == 0 && threadIdx.x < NEXP) g_cnt[threadIdx.x] = 0;
}

// ---------------- kernel 0b: split fp32 -> bf16 hi/lo, vectorized ----------------
__global__ void split_all_kernel(const float* __restrict__ x,  const float* __restrict__ W1,
                                 const float* __restrict__ W2, const float* __restrict__ Wm) {
    const int stride = gridDim.x * blockDim.x;
    const int t = blockIdx.x * blockDim.x + threadIdx.x;
#define SPLIT_LOOP(SRC, HI, LO, N)                                            \
    for (int i = t; i < (N) / 4; i += stride) {                               \
        const float4 v = ((const float4*)SRC)[i];                             \
        __nv_bfloat162 h01, h23, l01, l23;                                    \
        h01.x = __float2bfloat16_rn(v.x); h01.y = __float2bfloat16_rn(v.y);   \
        h23.x = __float2bfloat16_rn(v.z); h23.y = __float2bfloat16_rn(v.w);   \
        l01.x = __float2bfloat16_rn(v.x - __bfloat162float(h01.x));           \
        l01.y = __float2bfloat16_rn(v.y - __bfloat162float(h01.y));           \
        l23.x = __float2bfloat16_rn(v.z - __bfloat162float(h23.x));           \
        l23.y = __float2bfloat16_rn(v.w - __bfloat162float(h23.y));           \
        ((__nv_bfloat162*)HI)[2 * i]     = h01;                               \
        ((__nv_bfloat162*)HI)[2 * i + 1] = h23;                               \
        ((__nv_bfloat162*)LO)[2 * i]     = l01;                               \
        ((__nv_bfloat162*)LO)[2 * i + 1] = l23;                               \
    }
    SPLIT_LOOP(x,  g_xhi,  g_xlo,  NTOK * DIN)
    SPLIT_LOOP(W1, g_w1hi, g_w1lo, NEXP * HDIM * DIN)
    SPLIT_LOOP(W2, g_w2hi, g_w2lo, NEXP * CDIM * HDIM)
    SPLIT_LOOP(Wm, g_wmhi, g_wmlo, NEXP * TOUT * CDIM)
#undef SPLIT_LOOP
}

// ---------------- kernel 1: gating (one warp per token) ----------------
__global__ __launch_bounds__(256) void gate_kernel(const float* __restrict__ x,
                                                   const float* __restrict__ wg) {
    const int tok  = (blockIdx.x * blockDim.x + threadIdx.x) >> 5;
    const int lane = threadIdx.x & 31;
    if (tok >= NTOK) return;
    const float* xr = x + (size_t)tok * DIN;

    float acc[8];
#pragma unroll
    for (int e = 0; e < 8; e++) acc[e] = 0.f;

#pragma unroll
    for (int it = 0; it < DIN / 32; it++) {
        const int d = it * 32 + lane;
        const float xv = xr[d];
        const float4 w0 = *(const float4*)(wg + d * 8);
        const float4 w1 = *(const float4*)(wg + d * 8 + 4);
        acc[0] += xv * w0.x; acc[1] += xv * w0.y;
        acc[2] += xv * w0.z; acc[3] += xv * w0.w;
        acc[4] += xv * w1.x; acc[5] += xv * w1.y;
        acc[6] += xv * w1.z; acc[7] += xv * w1.w;
    }
#pragma unroll
    for (int e = 0; e < 8; e++)
#pragma unroll
        for (int off = 16; off; off >>= 1)
            acc[e] += __shfl_xor_sync(0xFFFFFFFFu, acc[e], off);

    if (lane == 0) {
        int i0 = 0; float v0 = acc[0];
#pragma unroll
        for (int e = 1; e < 8; e++) if (acc[e] > v0) { v0 = acc[e]; i0 = e; }
        int i1 = -1; float v1 = -3.4e38f;
#pragma unroll
        for (int e = 0; e < 8; e++)
            if (e != i0 && acc[e] > v1) { v1 = acc[e]; i1 = e; }
        const float tt = expf(v1 - v0);
        const float g0 = 1.f / (1.f + tt);
        const float g1 = tt / (1.f + tt);

        int s0 = atomicAdd(&g_cnt[i0], 1);
        g_tok[i0 * NTOK + s0]  = tok;
        g_gate[i0 * NTOK + s0] = g0;
        int s1 = atomicAdd(&g_cnt[i1], 1);
        g_tok[i1 * NTOK + s1]  = tok;
        g_gate[i1 * NTOK + s1] = g1;
    }
}

// ---------------- kernel 2: fc1 (split-bf16 mma, BN=128, cp.async) ----------------
__global__ __launch_bounds__(256, 2) void fc1_mma(const float* __restrict__ b1) {
    const int e   = blockIdx.z;
    const int cnt = g_cnt[e];
    const int m0  = blockIdx.x * 128;
    if (m0 >= cnt) return;
    const int n0  = blockIdx.y * 128;
    const int tid = threadIdx.x;

    extern __shared__ char dsm[];
    const uint32_t sb = smem_u32(dsm);

    const int arow = tid >> 1;
    int r = m0 + arow; if (r >= cnt) r = cnt - 1;
    const int tok = g_tok[e * NTOK + r];
    const __nv_bfloat16* aghi = g_xhi + (size_t)tok * DIN + (tid & 1) * 16;
    const __nv_bfloat16* aglo = g_xlo + (size_t)tok * DIN + (tid & 1) * 16;
    const int brow = tid >> 1;
    const __nv_bfloat16* bghi = g_w1hi + ((size_t)e * HDIM + n0 + brow) * DIN + (tid & 1) * 16;
    const __nv_bfloat16* bglo = g_w1lo + ((size_t)e * HDIM + n0 + brow) * DIN + (tid & 1) * 16;

    float acc[4][4][4] = {};
    run_mainloop_cp<DIN / 32, 128>(sb, aghi, aglo, bghi, bglo, acc);

    const int lane = tid & 31, wid = tid >> 5;
    const int warp_m = wid & 1, warp_n = wid >> 1;
#pragma unroll
    for (int nf = 0; nf < 4; nf++) {
        const int n = n0 + warp_n * 32 + nf * 8 + 2 * (lane & 3);
        const float bb0 = b1[e * HDIM + n];
        const float bb1 = b1[e * HDIM + n + 1];
#pragma unroll
        for (int mf = 0; mf < 4; mf++)
#pragma unroll
            for (int hr = 0; hr < 2; hr++) {
                const int m = m0 + warp_m * 64 + mf * 16 + (lane >> 2) + hr * 8;
                if (m < cnt) {
                    const float h0 = fmaxf(acc[mf][nf][2 * hr + 0] + bb0, 0.f);
                    const float h1 = fmaxf(acc[mf][nf][2 * hr + 1] + bb1, 0.f);
                    split_store2(g_Hhi, g_Hlo, ((size_t)e * NTOK + m) * HDIM + n, h0, h1);
                }
            }
    }
}

// ---------------- kernel 3: fc2 (split-bf16 mma + gate, BN=64, cp.async) ----------------
__global__ __launch_bounds__(256, 2) void fc2_mma(const float* __restrict__ b2) {
    const int e   = blockIdx.z;
    const int cnt = g_cnt[e];
    const int m0  = blockIdx.x * 128;
    if (m0 >= cnt) return;
    const int tid = threadIdx.x;

    extern __shared__ char dsm[];
    const uint32_t sb = smem_u32(dsm);

    const int arow = tid >> 1;
    const __nv_bfloat16* aghi = g_Hhi + ((size_t)e * NTOK + m0 + arow) * HDIM + (tid & 1) * 16;
    const __nv_bfloat16* aglo = g_Hlo + ((size_t)e * NTOK + m0 + arow) * HDIM + (tid & 1) * 16;
    const int brow = tid >> 2;
    const __nv_bfloat16* bghi = g_w2hi + ((size_t)e * CDIM + brow) * HDIM + (tid & 3) * 8;
    const __nv_bfloat16* bglo = g_w2lo + ((size_t)e * CDIM + brow) * HDIM + (tid & 3) * 8;

    float acc[4][2][4] = {};
    run_mainloop_cp<HDIM / 32, 64>(sb, aghi, aglo, bghi, bglo, acc);

    const int lane = tid & 31, wid = tid >> 5;
    const int warp_m = wid & 1, warp_n = wid >> 1;
#pragma unroll
    for (int nf = 0; nf < 2; nf++) {
        const int n = warp_n * 16 + nf * 8 + 2 * (lane & 3);
        const float bb0 = b2[e * CDIM + n];
        const float bb1 = b2[e * CDIM + n + 1];
#pragma unroll
        for (int mf = 0; mf < 4; mf++)
#pragma unroll
            for (int hr = 0; hr < 2; hr++) {
                const int m = m0 + warp_m * 64 + mf * 16 + (lane >> 2) + hr * 8;
                if (m < cnt) {
                    const float g = g_gate[e * NTOK + m];
                    const float o0 = (acc[mf][nf][2 * hr + 0] + bb0) * g;
                    const float o1 = (acc[mf][nf][2 * hr + 1] + bb1) * g;
                    split_store2(g_Ohi, g_Olo, ((size_t)e * NTOK + m) * CDIM + n, o0, o1);
                }
            }
    }
}

// ---------------- kernel 4: combine (split-bf16 mma + atomic scatter, BN=128, cp.async) ----------------
__global__ __launch_bounds__(256, 2) void combine_mma(float* __restrict__ y) {
    const int e   = blockIdx.z;
    const int cnt = g_cnt[e];
    const int m0  = blockIdx.x * 128;
    if (m0 >= cnt) return;
    const int n0  = blockIdx.y * 128;
    const int tid = threadIdx.x;

    extern __shared__ char dsm[];
    const uint32_t sb = smem_u32(dsm);

    const int arow = tid >> 1;
    const __nv_bfloat16* aghi = g_Ohi + ((size_t)e * NTOK + m0 + arow) * CDIM + (tid & 1) * 16;
    const __nv_bfloat16* aglo = g_Olo + ((size_t)e * NTOK + m0 + arow) * CDIM + (tid & 1) * 16;
    const int brow = tid >> 1;
    const __nv_bfloat16* bghi = g_wmhi + ((size_t)e * TOUT + n0 + brow) * CDIM + (tid & 1) * 16;
    const __nv_bfloat16* bglo = g_wmlo + ((size_t)e * TOUT + n0 + brow) * CDIM + (tid & 1) * 16;

    float acc[4][4][4] = {};
    run_mainloop_cp<CDIM / 32, 128>(sb, aghi, aglo, bghi, bglo, acc);

    const int lane = tid & 31, wid = tid >> 5;
    const int warp_m = wid & 1, warp_n = wid >> 1;
#pragma unroll
    for (int mf = 0; mf < 4; mf++)
#pragma unroll
        for (int hr = 0; hr < 2; hr++) {
            const int m = m0 + warp_m * 64 + mf * 16 + (lane >> 2) + hr * 8;
            if (m < cnt) {
                const int tok = g_tok[e * NTOK + m];
                float* yr = y + (size_t)tok * TOUT;
#pragma unroll
                for (int nf = 0; nf < 4; nf++) {
                    const int n = n0 + warp_n * 32 + nf * 8 + 2 * (lane & 3);
                    atomicAdd(yr + n,     acc[mf][nf][2 * hr + 0]);
                    atomicAdd(yr + n + 1, acc[mf][nf][2 * hr + 1]);
                }
            }
        }
}

// ---------------- kernel 5: EPS fixup (vectorized) ----------------
__global__ void eps_kernel(float4* __restrict__ y) {
    const int n = NTOK * TOUT / 4;
    for (int i = blockIdx.x * blockDim.x + threadIdx.x; i < n;
         i += gridDim.x * blockDim.x) {
        float4 v = y[i];
        bool fix = (v.x == 0.f) | (v.y == 0.f) | (v.z == 0.f) | (v.w == 0.f);
        if (fix) {
            if (v.x == 0.f) v.x = EPSV;
            if (v.y == 0.f) v.y = EPSV;
            if (v.z == 0.f) v.z = EPSV;
            if (v.w == 0.f) v.w = EPSV;
            y[i] = v;
        }
    }
}

// ---------------- launch ----------------
extern "C" void kernel_launch(void* const* d_in, const int* in_sizes, int n_in,
                              void* d_out, int out_size) {
    const float* x  = (const float*)d_in[0];
    // d_in[1] = labels (int64) — unused by the reference computation
    const float* wg = (const float*)d_in[2];
    const float* W1 = (const float*)d_in[3];
    const float* b1 = (const float*)d_in[4];
    const float* W2 = (const float*)d_in[5];
    const float* b2 = (const float*)d_in[6];
    const float* Wm = (const float*)d_in[7];
    float* y = (float*)d_out;

    cudaFuncSetAttribute(fc1_mma,     cudaFuncAttributeMaxDynamicSharedMemorySize, SMEM_128);
    cudaFuncSetAttribute(fc2_mma,     cudaFuncAttributeMaxDynamicSharedMemorySize, SMEM_64);
    cudaFuncSetAttribute(combine_mma, cudaFuncAttributeMaxDynamicSharedMemorySize, SMEM_128);

    zero_kernel<<<256, 256>>>((float4*)y);
    split_all_kernel<<<2048, 256>>>(x, W1, W2, Wm);
    gate_kernel<<<NTOK / 8, 256>>>(x, wg);

    dim3 g1(NTOK / 128, HDIM / 128, NEXP);  // (64, 2, 8)
    fc1_mma<<<g1, 256, SMEM_128>>>(b1);

    dim3 g2(NTOK / 128, 1, NEXP);           // (64, 1, 8)
    fc2_mma<<<g2, 256, SMEM_64>>>(b2);

    dim3 g3(NTOK / 128, TOUT / 128, NEXP);  // (64, 4, 8)
    combine_mma<<<g3, 256, SMEM_128>>>(y);

    eps_kernel<<<512, 256>>>((float4*)y);
}

// round 10
// speedup vs baseline: 2.1414x; 1.0004x over previous
#include <cuda_runtime.h>
#include <cuda_bf16.h>
#include <math.h>
#include <stdint.h>

#define NTOK 8192
#define DIN  768
#define HDIM 256
#define NEXP 8
#define CDIM 64
#define TOUT 512
#define EPSV 2.2204460492503131e-16f

// ---------------- static device scratch (allocation-free rule) ----------------
__device__ int           g_cnt[NEXP];
__device__ int           g_tok[NEXP * NTOK];
__device__ unsigned char g_slot[NEXP * NTOK];
__device__ float         g_gate[NEXP * NTOK];
__device__ float         g_part[2ull * NTOK * TOUT];   // 33.5 MB partial sums

__device__ __nv_bfloat16 g_xhi[NTOK * DIN],        g_xlo[NTOK * DIN];
__device__ __nv_bfloat16 g_w1hi[NEXP * HDIM * DIN], g_w1lo[NEXP * HDIM * DIN];
__device__ __nv_bfloat16 g_w2hi[NEXP * CDIM * HDIM], g_w2lo[NEXP * CDIM * HDIM];
__device__ __nv_bfloat16 g_wmhi[NEXP * TOUT * CDIM], g_wmlo[NEXP * TOUT * CDIM];
__device__ __nv_bfloat16 g_Hhi[(size_t)NEXP * NTOK * HDIM], g_Hlo[(size_t)NEXP * NTOK * HDIM];
__device__ __nv_bfloat16 g_Ohi[(size_t)NEXP * NTOK * CDIM], g_Olo[(size_t)NEXP * NTOK * CDIM];

// ---------------- helpers ----------------
__device__ __forceinline__ uint32_t smem_u32(const void* p) {
    return (uint32_t)__cvta_generic_to_shared(p);
}
__device__ __forceinline__ void ldmx4(uint32_t* r, uint32_t addr) {
    asm volatile("ldmatrix.sync.aligned.m8n8.x4.shared.b16 {%0,%1,%2,%3}, [%4];\n"
                 : "=r"(r[0]), "=r"(r[1]), "=r"(r[2]), "=r"(r[3]) : "r"(addr));
}
__device__ __forceinline__ void mma16816(float* c, const uint32_t* a, uint32_t b0, uint32_t b1) {
    asm volatile(
        "mma.sync.aligned.m16n8k16.row.col.f32.bf16.bf16.f32 "
        "{%0,%1,%2,%3}, {%4,%5,%6,%7}, {%8,%9}, {%0,%1,%2,%3};\n"
        : "+f"(c[0]), "+f"(c[1]), "+f"(c[2]), "+f"(c[3])
        : "r"(a[0]), "r"(a[1]), "r"(a[2]), "r"(a[3]), "r"(b0), "r"(b1));
}
__device__ __forceinline__ void cp16(uint32_t dst, const void* src) {
    asm volatile("cp.async.cg.shared.global [%0], [%1], 16;" :: "r"(dst), "l"(src));
}
#define CP_COMMIT() asm volatile("cp.async.commit_group;" ::: "memory")
#define CP_WAIT0()  asm volatile("cp.async.wait_group 0;" ::: "memory")

__device__ __forceinline__ void split_store2(__nv_bfloat16* hi, __nv_bfloat16* lo,
                                             size_t off, float v0, float v1) {
    __nv_bfloat16 h0 = __float2bfloat16_rn(v0), h1 = __float2bfloat16_rn(v1);
    __nv_bfloat162 th; th.x = h0; th.y = h1;
    __nv_bfloat162 tl;
    tl.x = __float2bfloat16_rn(v0 - __bfloat162float(h0));
    tl.y = __float2bfloat16_rn(v1 - __bfloat162float(h1));
    *(__nv_bfloat162*)(hi + off) = th;
    *(__nv_bfloat162*)(lo + off) = tl;
}

// ---------------- smem geometry ----------------
#define ASZ 10240
#define BSZ(BN) ((BN) * 80)
#define STGSZ(BN) (2 * ASZ + 2 * BSZ(BN))
#define SMEM_128 (2 * STGSZ(128))   // 81920
#define SMEM_64  (2 * STGSZ(64))    // 61440

// ---------------- shared mainloop (cp.async, single barrier per chunk) ----------------
// Ordering per chunk: wait0 -> __syncthreads -> issue loads ch+1 -> MMA ch.
// Loads for ch+1 overwrite the buffer read at ch-1; the barrier guarantees all
// warps completed ch-1 MMAs before any overwrite. Loads for ch+1 stay in flight
// through the whole MMA phase of ch.
template <int NCH, int BN>
__device__ __forceinline__ void run_mainloop_cp(
    uint32_t sb,
    const __nv_bfloat16* aghi, const __nv_bfloat16* aglo,
    const __nv_bfloat16* bghi, const __nv_bfloat16* bglo,
    float (&acc)[4][BN / 32][4])
{
    constexpr int NF = BN / 32;
    constexpr int BS = BSZ(BN);
    constexpr int ST = STGSZ(BN);
    const int tid  = threadIdx.x;
    const int lane = tid & 31;
    const int wid  = tid >> 5;
    const int warp_m = wid & 1;
    const int warp_n = wid >> 1;

    const uint32_t a_off = (tid >> 1) * 80 + (tid & 1) * 32;
    const uint32_t b_off = (BN == 128) ? ((tid >> 1) * 80 + (tid & 1) * 32)
                                       : ((tid >> 2) * 80 + (tid & 3) * 16);

    const int ar = warp_m * 64 + ((lane >> 3) & 1) * 8 + (lane & 7);
    const int ac = (lane >> 4) * 8;
    const uint32_t la = sb + ar * 80 + ac * 2;
    const int br = warp_n * (BN / 4) + ((lane >> 4) << 3) + (lane & 7);
    const int bc = ((lane >> 3) & 1) * 8;
    const uint32_t lb = sb + 2 * ASZ + br * 80 + bc * 2;

    auto load_stage = [&](int s) {
        const uint32_t st = sb + s * ST;
        cp16(st + a_off,            aghi);
        cp16(st + a_off + 16,       aghi + 8);
        cp16(st + ASZ + a_off,      aglo);
        cp16(st + ASZ + a_off + 16, aglo + 8);
        if (BN == 128) {
            cp16(st + 2 * ASZ + b_off,           bghi);
            cp16(st + 2 * ASZ + b_off + 16,      bghi + 8);
            cp16(st + 2 * ASZ + BS + b_off,      bglo);
            cp16(st + 2 * ASZ + BS + b_off + 16, bglo + 8);
        } else {
            cp16(st + 2 * ASZ + b_off,      bghi);
            cp16(st + 2 * ASZ + BS + b_off, bglo);
        }
        aghi += 32; aglo += 32; bghi += 32; bglo += 32;
    };

    load_stage(0);
    CP_COMMIT();

    for (int ch = 0; ch < NCH; ch++) {
        CP_WAIT0();
        __syncthreads();
        if (ch + 1 < NCH) {
            load_stage((ch + 1) & 1);
            CP_COMMIT();
        }

        const uint32_t sa  = la + (ch & 1) * ST;
        const uint32_t sbb = lb + (ch & 1) * ST;
#pragma unroll
        for (int kk = 0; kk < 2; kk++) {
            uint32_t bh[2 * NF], bl[2 * NF];
            ldmx4(bh, sbb + kk * 32);
            ldmx4(bl, sbb + BS + kk * 32);
            if (NF == 4) {
                ldmx4(bh + 4, sbb + 1280 + kk * 32);
                ldmx4(bl + 4, sbb + BS + 1280 + kk * 32);
            }
#pragma unroll
            for (int mf = 0; mf < 4; mf++) {
                uint32_t ah[4], al[4];
                ldmx4(ah, sa + (uint32_t)(mf * 1280) + kk * 32);
                ldmx4(al, sa + ASZ + (uint32_t)(mf * 1280) + kk * 32);
#pragma unroll
                for (int nf = 0; nf < NF; nf++)
                    mma16816(acc[mf][nf], ah, bh[2 * nf], bh[2 * nf + 1]);
#pragma unroll
                for (int nf = 0; nf < NF; nf++)
                    mma16816(acc[mf][nf], ah, bl[2 * nf], bl[2 * nf + 1]);
#pragma unroll
                for (int nf = 0; nf < NF; nf++)
                    mma16816(acc[mf][nf], al, bh[2 * nf], bh[2 * nf + 1]);
            }
        }
    }
}

// ---------------- kernel 0: split weights -> bf16 hi/lo + zero counts ----------------
__global__ void split_w_kernel(const float* __restrict__ W1,
                               const float* __restrict__ W2, const float* __restrict__ Wm) {
    if (blockIdx.x == 0 && threadIdx.x < NEXP) g_cnt[threadIdx.x] = 0;
    const int stride = gridDim.x * blockDim.x;
    const int t = blockIdx.x * blockDim.x + threadIdx.x;
#define SPLIT_LOOP(SRC, HI, LO, N)                                            \
    for (int i = t; i < (N) / 4; i += stride) {                               \
        const float4 v = ((const float4*)SRC)[i];                             \
        __nv_bfloat162 h01, h23, l01, l23;                                    \
        h01.x = __float2bfloat16_rn(v.x); h01.y = __float2bfloat16_rn(v.y);   \
        h23.x = __float2bfloat16_rn(v.z); h23.y = __float2bfloat16_rn(v.w);   \
        l01.x = __float2bfloat16_rn(v.x - __bfloat162float(h01.x));           \
        l01.y = __float2bfloat16_rn(v.y - __bfloat162float(h01.y));           \
        l23.x = __float2bfloat16_rn(v.z - __bfloat162float(h23.x));           \
        l23.y = __float2bfloat16_rn(v.w - __bfloat162float(h23.y));           \
        ((__nv_bfloat162*)HI)[2 * i]     = h01;                               \
        ((__nv_bfloat162*)HI)[2 * i + 1] = h23;                               \
        ((__nv_bfloat162*)LO)[2 * i]     = l01;                               \
        ((__nv_bfloat162*)LO)[2 * i + 1] = l23;                               \
    }
    SPLIT_LOOP(W1, g_w1hi, g_w1lo, NEXP * HDIM * DIN)
    SPLIT_LOOP(W2, g_w2hi, g_w2lo, NEXP * CDIM * HDIM)
    SPLIT_LOOP(Wm, g_wmhi, g_wmlo, NEXP * TOUT * CDIM)
#undef SPLIT_LOOP
}

// ---------------- kernel 1: gating + x split (one warp per token) ----------------
__global__ __launch_bounds__(256) void gate_kernel(const float* __restrict__ x,
                                                   const float* __restrict__ wg) {
    const int tok  = (blockIdx.x * blockDim.x + threadIdx.x) >> 5;
    const int lane = threadIdx.x & 31;
    if (tok >= NTOK) return;
    const float* xr = x + (size_t)tok * DIN;
    __nv_bfloat16* xh = g_xhi + (size_t)tok * DIN;
    __nv_bfloat16* xl = g_xlo + (size_t)tok * DIN;

    float acc[8];
#pragma unroll
    for (int e = 0; e < 8; e++) acc[e] = 0.f;

#pragma unroll
    for (int it = 0; it < DIN / 32; it++) {
        const int d = it * 32 + lane;
        const float xv = xr[d];
        // fused x split (same values/rounding as before)
        const __nv_bfloat16 h = __float2bfloat16_rn(xv);
        xh[d] = h;
        xl[d] = __float2bfloat16_rn(xv - __bfloat162float(h));
        const float4 w0 = *(const float4*)(wg + d * 8);
        const float4 w1 = *(const float4*)(wg + d * 8 + 4);
        acc[0] += xv * w0.x; acc[1] += xv * w0.y;
        acc[2] += xv * w0.z; acc[3] += xv * w0.w;
        acc[4] += xv * w1.x; acc[5] += xv * w1.y;
        acc[6] += xv * w1.z; acc[7] += xv * w1.w;
    }
#pragma unroll
    for (int e = 0; e < 8; e++)
#pragma unroll
        for (int off = 16; off; off >>= 1)
            acc[e] += __shfl_xor_sync(0xFFFFFFFFu, acc[e], off);

    if (lane == 0) {
        int i0 = 0; float v0 = acc[0];
#pragma unroll
        for (int e = 1; e < 8; e++) if (acc[e] > v0) { v0 = acc[e]; i0 = e; }
        int i1 = -1; float v1 = -3.4e38f;
#pragma unroll
        for (int e = 0; e < 8; e++)
            if (e != i0 && acc[e] > v1) { v1 = acc[e]; i1 = e; }
        const float tt = expf(v1 - v0);
        const float g0 = 1.f / (1.f + tt);
        const float g1 = tt / (1.f + tt);

        int s0 = atomicAdd(&g_cnt[i0], 1);
        g_tok[i0 * NTOK + s0]  = tok;
        g_slot[i0 * NTOK + s0] = 0;
        g_gate[i0 * NTOK + s0] = g0;
        int s1 = atomicAdd(&g_cnt[i1], 1);
        g_tok[i1 * NTOK + s1]  = tok;
        g_slot[i1 * NTOK + s1] = 1;
        g_gate[i1 * NTOK + s1] = g1;
    }
}

// ---------------- kernel 2: fc1 (split-bf16 mma, BN=128, cp.async) ----------------
__global__ __launch_bounds__(256, 2) void fc1_mma(const float* __restrict__ b1) {
    const int e   = blockIdx.z;
    const int cnt = g_cnt[e];
    const int m0  = blockIdx.x * 128;
    if (m0 >= cnt) return;
    const int n0  = blockIdx.y * 128;
    const int tid = threadIdx.x;

    extern __shared__ char dsm[];
    const uint32_t sb = smem_u32(dsm);

    const int arow = tid >> 1;
    int r = m0 + arow; if (r >= cnt) r = cnt - 1;
    const int tok = g_tok[e * NTOK + r];
    const __nv_bfloat16* aghi = g_xhi + (size_t)tok * DIN + (tid & 1) * 16;
    const __nv_bfloat16* aglo = g_xlo + (size_t)tok * DIN + (tid & 1) * 16;
    const int brow = tid >> 1;
    const __nv_bfloat16* bghi = g_w1hi + ((size_t)e * HDIM + n0 + brow) * DIN + (tid & 1) * 16;
    const __nv_bfloat16* bglo = g_w1lo + ((size_t)e * HDIM + n0 + brow) * DIN + (tid & 1) * 16;

    float acc[4][4][4] = {};
    run_mainloop_cp<DIN / 32, 128>(sb, aghi, aglo, bghi, bglo, acc);

    const int lane = tid & 31, wid = tid >> 5;
    const int warp_m = wid & 1, warp_n = wid >> 1;
#pragma unroll
    for (int nf = 0; nf < 4; nf++) {
        const int n = n0 + warp_n * 32 + nf * 8 + 2 * (lane & 3);
        const float bb0 = b1[e * HDIM + n];
        const float bb1 = b1[e * HDIM + n + 1];
#pragma unroll
        for (int mf = 0; mf < 4; mf++)
#pragma unroll
            for (int hr = 0; hr < 2; hr++) {
                const int m = m0 + warp_m * 64 + mf * 16 + (lane >> 2) + hr * 8;
                if (m < cnt) {
                    const float h0 = fmaxf(acc[mf][nf][2 * hr + 0] + bb0, 0.f);
                    const float h1 = fmaxf(acc[mf][nf][2 * hr + 1] + bb1, 0.f);
                    split_store2(g_Hhi, g_Hlo, ((size_t)e * NTOK + m) * HDIM + n, h0, h1);
                }
            }
    }
}

// ---------------- kernel 3: fc2 (split-bf16 mma + gate, BN=64, cp.async) ----------------
__global__ __launch_bounds__(256, 2) void fc2_mma(const float* __restrict__ b2) {
    const int e   = blockIdx.z;
    const int cnt = g_cnt[e];
    const int m0  = blockIdx.x * 128;
    if (m0 >= cnt) return;
    const int tid = threadIdx.x;

    extern __shared__ char dsm[];
    const uint32_t sb = smem_u32(dsm);

    const int arow = tid >> 1;
    const __nv_bfloat16* aghi = g_Hhi + ((size_t)e * NTOK + m0 + arow) * HDIM + (tid & 1) * 16;
    const __nv_bfloat16* aglo = g_Hlo + ((size_t)e * NTOK + m0 + arow) * HDIM + (tid & 1) * 16;
    const int brow = tid >> 2;
    const __nv_bfloat16* bghi = g_w2hi + ((size_t)e * CDIM + brow) * HDIM + (tid & 3) * 8;
    const __nv_bfloat16* bglo = g_w2lo + ((size_t)e * CDIM + brow) * HDIM + (tid & 3) * 8;

    float acc[4][2][4] = {};
    run_mainloop_cp<HDIM / 32, 64>(sb, aghi, aglo, bghi, bglo, acc);

    const int lane = tid & 31, wid = tid >> 5;
    const int warp_m = wid & 1, warp_n = wid >> 1;
#pragma unroll
    for (int nf = 0; nf < 2; nf++) {
        const int n = warp_n * 16 + nf * 8 + 2 * (lane & 3);
        const float bb0 = b2[e * CDIM + n];
        const float bb1 = b2[e * CDIM + n + 1];
#pragma unroll
        for (int mf = 0; mf < 4; mf++)
#pragma unroll
            for (int hr = 0; hr < 2; hr++) {
                const int m = m0 + warp_m * 64 + mf * 16 + (lane >> 2) + hr * 8;
                if (m < cnt) {
                    const float g = g_gate[e * NTOK + m];
                    const float o0 = (acc[mf][nf][2 * hr + 0] + bb0) * g;
                    const float o1 = (acc[mf][nf][2 * hr + 1] + bb1) * g;
                    split_store2(g_Ohi, g_Olo, ((size_t)e * NTOK + m) * CDIM + n, o0, o1);
                }
            }
    }
}

// ---------------- kernel 4: combine (split-bf16 mma -> partial buffers, BN=128) ----------------
__global__ __launch_bounds__(256, 2) void combine_mma() {
    const int e   = blockIdx.z;
    const int cnt = g_cnt[e];
    const int m0  = blockIdx.x * 128;
    if (m0 >= cnt) return;
    const int n0  = blockIdx.y * 128;
    const int tid = threadIdx.x;

    extern __shared__ char dsm[];
    const uint32_t sb = smem_u32(dsm);

    const int arow = tid >> 1;
    const __nv_bfloat16* aghi = g_Ohi + ((size_t)e * NTOK + m0 + arow) * CDIM + (tid & 1) * 16;
    const __nv_bfloat16* aglo = g_Olo + ((size_t)e * NTOK + m0 + arow) * CDIM + (tid & 1) * 16;
    const int brow = tid >> 1;
    const __nv_bfloat16* bghi = g_wmhi + ((size_t)e * TOUT + n0 + brow) * CDIM + (tid & 1) * 16;
    const __nv_bfloat16* bglo = g_wmlo + ((size_t)e * TOUT + n0 + brow) * CDIM + (tid & 1) * 16;

    float acc[4][4][4] = {};
    run_mainloop_cp<CDIM / 32, 128>(sb, aghi, aglo, bghi, bglo, acc);

    const int lane = tid & 31, wid = tid >> 5;
    const int warp_m = wid & 1, warp_n = wid >> 1;
#pragma unroll
    for (int mf = 0; mf < 4; mf++)
#pragma unroll
        for (int hr = 0; hr < 2; hr++) {
            const int m = m0 + warp_m * 64 + mf * 16 + (lane >> 2) + hr * 8;
            if (m < cnt) {
                const int tok = g_tok[e * NTOK + m];
                const int k   = g_slot[e * NTOK + m];
                float* yr = g_part + ((size_t)k * NTOK + tok) * TOUT + n0;
#pragma unroll
                for (int nf = 0; nf < 4; nf++) {
                    const int n = warp_n * 32 + nf * 8 + 2 * (lane & 3);
                    float2 v;
                    v.x = acc[mf][nf][2 * hr + 0];
                    v.y = acc[mf][nf][2 * hr + 1];
                    *(float2*)(yr + n) = v;
                }
            }
        }
}

// ---------------- kernel 5: finish — y = p0 + p1, EPS fixup (vectorized) ----------------
__global__ void finish_kernel(float4* __restrict__ y) {
    const int n = NTOK * TOUT / 4;
    const float4* p0 = (const float4*)g_part;
    const float4* p1 = (const float4*)(g_part + (size_t)NTOK * TOUT);
    for (int i = blockIdx.x * blockDim.x + threadIdx.x; i < n;
         i += gridDim.x * blockDim.x) {
        const float4 a = p0[i];
        const float4 b = p1[i];
        float4 v;
        v.x = a.x + b.x; v.y = a.y + b.y; v.z = a.z + b.z; v.w = a.w + b.w;
        if (v.x == 0.f) v.x = EPSV;
        if (v.y == 0.f) v.y = EPSV;
        if (v.z == 0.f) v.z = EPSV;
        if (v.w == 0.f) v.w = EPSV;
        y[i] = v;
    }
}

// ---------------- launch ----------------
extern "C" void kernel_launch(void* const* d_in, const int* in_sizes, int n_in,
                              void* d_out, int out_size) {
    const float* x  = (const float*)d_in[0];
    // d_in[1] = labels (int64) — unused by the reference computation
    const float* wg = (const float*)d_in[2];
    const float* W1 = (const float*)d_in[3];
    const float* b1 = (const float*)d_in[4];
    const float* W2 = (const float*)d_in[5];
    const float* b2 = (const float*)d_in[6];
    const float* Wm = (const float*)d_in[7];
    float* y = (float*)d_out;

    cudaFuncSetAttribute(fc1_mma,     cudaFuncAttributeMaxDynamicSharedMemorySize, SMEM_128);
    cudaFuncSetAttribute(fc2_mma,     cudaFuncAttributeMaxDynamicSharedMemorySize, SMEM_64);
    cudaFuncSetAttribute(combine_mma, cudaFuncAttributeMaxDynamicSharedMemorySize, SMEM_128);

    split_w_kernel<<<512, 256>>>(W1, W2, Wm);
    gate_kernel<<<NTOK / 8, 256>>>(x, wg);

    dim3 g1(NTOK / 128, HDIM / 128, NEXP);  // (64, 2, 8)
    fc1_mma<<<g1, 256, SMEM_128>>>(b1);

    dim3 g2(NTOK / 128, 1, NEXP);           // (64, 1, 8)
    fc2_mma<<<g2, 256, SMEM_64>>>(b2);

    dim3 g3(NTOK / 128, TOUT / 128, NEXP);  // (64, 4, 8)
    combine_mma<<<g3, 256, SMEM_128>>>();

    finish_kernel<<<512, 256>>>((float4*)y);
}

// round 11
// speedup vs baseline: 2.3975x; 1.1196x over previous
#include <cuda_runtime.h>
#include <cuda_bf16.h>
#include <math.h>
#include <stdint.h>

#define NTOK 8192
#define DIN  768
#define HDIM 256
#define NEXP 8
#define CDIM 64
#define TOUT 512
#define EPSV 2.2204460492503131e-16f

// ---------------- static device scratch (allocation-free rule) ----------------
__device__ int           g_cnt[NEXP];            // zeroed at end of previous launch
__device__ int           g_tok[NEXP * NTOK];
__device__ unsigned char g_slot[NEXP * NTOK];
__device__ float         g_gate[NEXP * NTOK];
__device__ float         g_part[2ull * NTOK * TOUT];

__device__ __nv_bfloat16 g_xhi[NTOK * DIN],        g_xlo[NTOK * DIN];
__device__ __nv_bfloat16 g_w1hi[NEXP * HDIM * DIN], g_w1lo[NEXP * HDIM * DIN];
__device__ __nv_bfloat16 g_w2hi[NEXP * CDIM * HDIM], g_w2lo[NEXP * CDIM * HDIM];
__device__ __nv_bfloat16 g_wmhi[NEXP * TOUT * CDIM], g_wmlo[NEXP * TOUT * CDIM];
__device__ __nv_bfloat16 g_Hhi[(size_t)NEXP * NTOK * HDIM], g_Hlo[(size_t)NEXP * NTOK * HDIM];
__device__ __nv_bfloat16 g_Ohi[(size_t)NEXP * NTOK * CDIM], g_Olo[(size_t)NEXP * NTOK * CDIM];

// ---------------- helpers ----------------
__device__ __forceinline__ uint32_t smem_u32(const void* p) {
    return (uint32_t)__cvta_generic_to_shared(p);
}
__device__ __forceinline__ void ldmx4(uint32_t* r, uint32_t addr) {
    asm volatile("ldmatrix.sync.aligned.m8n8.x4.shared.b16 {%0,%1,%2,%3}, [%4];\n"
                 : "=r"(r[0]), "=r"(r[1]), "=r"(r[2]), "=r"(r[3]) : "r"(addr));
}
__device__ __forceinline__ void mma16816(float* c, const uint32_t* a, uint32_t b0, uint32_t b1) {
    asm volatile(
        "mma.sync.aligned.m16n8k16.row.col.f32.bf16.bf16.f32 "
        "{%0,%1,%2,%3}, {%4,%5,%6,%7}, {%8,%9}, {%0,%1,%2,%3};\n"
        : "+f"(c[0]), "+f"(c[1]), "+f"(c[2]), "+f"(c[3])
        : "r"(a[0]), "r"(a[1]), "r"(a[2]), "r"(a[3]), "r"(b0), "r"(b1));
}
__device__ __forceinline__ void cp16(uint32_t dst, const void* src) {
    asm volatile("cp.async.cg.shared.global [%0], [%1], 16;" :: "r"(dst), "l"(src));
}
#define CP_COMMIT() asm volatile("cp.async.commit_group;" ::: "memory")
#define CP_WAIT0()  asm volatile("cp.async.wait_group 0;" ::: "memory")

__device__ __forceinline__ void split_store2(__nv_bfloat16* hi, __nv_bfloat16* lo,
                                             size_t off, float v0, float v1) {
    __nv_bfloat16 h0 = __float2bfloat16_rn(v0), h1 = __float2bfloat16_rn(v1);
    __nv_bfloat162 th; th.x = h0; th.y = h1;
    __nv_bfloat162 tl;
    tl.x = __float2bfloat16_rn(v0 - __bfloat162float(h0));
    tl.y = __float2bfloat16_rn(v1 - __bfloat162float(h1));
    *(__nv_bfloat162*)(hi + off) = th;
    *(__nv_bfloat162*)(lo + off) = tl;
}

// ---------------- smem geometry (row pitch 80B, conflict-free ldmatrix) ----------------
#define TSZ(R) ((R) * 80)
#define STG(BM, BN) (2 * TSZ(BM) + 2 * TSZ(BN))
#define SMEM_FC1 (2 * STG(128, 128))   // 81920
#define SMEM_FC2 (2 * STG(64, 64))     // 40960
#define SMEM_CMB (2 * STG(64, 128))    // 61440

// ---------------- shared mainloop (cp.async double-buffered, 1 barrier/chunk) ----------------
// Block tile BM x BN x 32K, 8 warps as 2(M) x 4(N); per-warp tile (BM/2) x (BN/4).
// MMA order per accumulator: hh -> hl -> lh (bitwise-stable across tile shapes).
template <int NCH, int BM, int BN>
__device__ __forceinline__ void run_mainloop_cp(
    uint32_t sb,
    const __nv_bfloat16* aghi, const __nv_bfloat16* aglo,
    const __nv_bfloat16* bghi, const __nv_bfloat16* bglo,
    float (&acc)[BM / 32][BN / 32][4])
{
    constexpr int MF = BM / 32;
    constexpr int NF = BN / 32;
    constexpr int AS = TSZ(BM);
    constexpr int BS = TSZ(BN);
    constexpr int ST = STG(BM, BN);
    const int tid  = threadIdx.x;
    const int lane = tid & 31;
    const int wid  = tid >> 5;
    const int warp_m = wid & 1;
    const int warp_n = wid >> 1;

    const uint32_t a_off = (BM == 128) ? ((tid >> 1) * 80 + (tid & 1) * 32)
                                       : ((tid >> 2) * 80 + (tid & 3) * 16);
    const uint32_t b_off = (BN == 128) ? ((tid >> 1) * 80 + (tid & 1) * 32)
                                       : ((tid >> 2) * 80 + (tid & 3) * 16);

    const int ar = warp_m * (BM / 2) + ((lane >> 3) & 1) * 8 + (lane & 7);
    const int ac = (lane >> 4) * 8;
    const uint32_t la = sb + ar * 80 + ac * 2;
    const int br = warp_n * (BN / 4) + ((lane >> 4) << 3) + (lane & 7);
    const int bc = ((lane >> 3) & 1) * 8;
    const uint32_t lb = sb + 2 * AS + br * 80 + bc * 2;

    auto load_stage = [&](int s) {
        const uint32_t st = sb + s * ST;
        if (BM == 128) {
            cp16(st + a_off,           aghi);
            cp16(st + a_off + 16,      aghi + 8);
            cp16(st + AS + a_off,      aglo);
            cp16(st + AS + a_off + 16, aglo + 8);
        } else {
            cp16(st + a_off,      aghi);
            cp16(st + AS + a_off, aglo);
        }
        if (BN == 128) {
            cp16(st + 2 * AS + b_off,           bghi);
            cp16(st + 2 * AS + b_off + 16,      bghi + 8);
            cp16(st + 2 * AS + BS + b_off,      bglo);
            cp16(st + 2 * AS + BS + b_off + 16, bglo + 8);
        } else {
            cp16(st + 2 * AS + b_off,      bghi);
            cp16(st + 2 * AS + BS + b_off, bglo);
        }
        aghi += 32; aglo += 32; bghi += 32; bglo += 32;
    };

    load_stage(0);
    CP_COMMIT();

    for (int ch = 0; ch < NCH; ch++) {
        CP_WAIT0();
        __syncthreads();
        if (ch + 1 < NCH) {
            load_stage((ch + 1) & 1);
            CP_COMMIT();
        }

        const uint32_t sa  = la + (ch & 1) * ST;
        const uint32_t sbb = lb + (ch & 1) * ST;
#pragma unroll
        for (int kk = 0; kk < 2; kk++) {
            uint32_t bh[2 * NF], bl[2 * NF];
            ldmx4(bh, sbb + kk * 32);
            ldmx4(bl, sbb + BS + kk * 32);
            if (NF == 4) {
                ldmx4(bh + 4, sbb + 1280 + kk * 32);
                ldmx4(bl + 4, sbb + BS + 1280 + kk * 32);
            }
#pragma unroll
            for (int mf = 0; mf < MF; mf++) {
                uint32_t ah[4], al[4];
                ldmx4(ah, sa + (uint32_t)(mf * 1280) + kk * 32);
                ldmx4(al, sa + AS + (uint32_t)(mf * 1280) + kk * 32);
#pragma unroll
                for (int nf = 0; nf < NF; nf++)
                    mma16816(acc[mf][nf], ah, bh[2 * nf], bh[2 * nf + 1]);
#pragma unroll
                for (int nf = 0; nf < NF; nf++)
                    mma16816(acc[mf][nf], ah, bl[2 * nf], bl[2 * nf + 1]);
#pragma unroll
                for (int nf = 0; nf < NF; nf++)
                    mma16816(acc[mf][nf], al, bh[2 * nf], bh[2 * nf + 1]);
            }
        }
    }
}

// ---------------- kernel 1: prep = gating + x split (blocks 0..1023)
//                            ∥ weight split (blocks 1024..1535) ----------------
__global__ __launch_bounds__(256) void prep_kernel(
    const float* __restrict__ x,  const float* __restrict__ wg,
    const float* __restrict__ W1, const float* __restrict__ W2,
    const float* __restrict__ Wm)
{
    if (blockIdx.x < NTOK / 8) {
        // ---- gating, one warp per token; fused x hi/lo split ----
        const int tok  = (blockIdx.x * blockDim.x + threadIdx.x) >> 5;
        const int lane = threadIdx.x & 31;
        const float* xr = x + (size_t)tok * DIN;
        __nv_bfloat16* xh = g_xhi + (size_t)tok * DIN;
        __nv_bfloat16* xl = g_xlo + (size_t)tok * DIN;

        float acc[8];
#pragma unroll
        for (int e = 0; e < 8; e++) acc[e] = 0.f;

#pragma unroll
        for (int it = 0; it < DIN / 32; it++) {
            const int d = it * 32 + lane;
            const float xv = xr[d];
            const __nv_bfloat16 h = __float2bfloat16_rn(xv);
            xh[d] = h;
            xl[d] = __float2bfloat16_rn(xv - __bfloat162float(h));
            const float4 w0 = *(const float4*)(wg + d * 8);
            const float4 w1 = *(const float4*)(wg + d * 8 + 4);
            acc[0] += xv * w0.x; acc[1] += xv * w0.y;
            acc[2] += xv * w0.z; acc[3] += xv * w0.w;
            acc[4] += xv * w1.x; acc[5] += xv * w1.y;
            acc[6] += xv * w1.z; acc[7] += xv * w1.w;
        }
#pragma unroll
        for (int e = 0; e < 8; e++)
#pragma unroll
            for (int off = 16; off; off >>= 1)
                acc[e] += __shfl_xor_sync(0xFFFFFFFFu, acc[e], off);

        if (lane == 0) {
            int i0 = 0; float v0 = acc[0];
#pragma unroll
            for (int e = 1; e < 8; e++) if (acc[e] > v0) { v0 = acc[e]; i0 = e; }
            int i1 = -1; float v1 = -3.4e38f;
#pragma unroll
            for (int e = 0; e < 8; e++)
                if (e != i0 && acc[e] > v1) { v1 = acc[e]; i1 = e; }
            const float tt = expf(v1 - v0);
            const float g0 = 1.f / (1.f + tt);
            const float g1 = tt / (1.f + tt);

            int s0 = atomicAdd(&g_cnt[i0], 1);
            g_tok[i0 * NTOK + s0]  = tok;
            g_slot[i0 * NTOK + s0] = 0;
            g_gate[i0 * NTOK + s0] = g0;
            int s1 = atomicAdd(&g_cnt[i1], 1);
            g_tok[i1 * NTOK + s1]  = tok;
            g_slot[i1 * NTOK + s1] = 1;
            g_gate[i1 * NTOK + s1] = g1;
        }
    } else {
        // ---- weight hi/lo split, vectorized ----
        const int stride = 512 * 256;
        const int t = (blockIdx.x - NTOK / 8) * 256 + threadIdx.x;
#define SPLIT_LOOP(SRC, HI, LO, N)                                            \
    for (int i = t; i < (N) / 4; i += stride) {                               \
        const float4 v = ((const float4*)SRC)[i];                             \
        __nv_bfloat162 h01, h23, l01, l23;                                    \
        h01.x = __float2bfloat16_rn(v.x); h01.y = __float2bfloat16_rn(v.y);   \
        h23.x = __float2bfloat16_rn(v.z); h23.y = __float2bfloat16_rn(v.w);   \
        l01.x = __float2bfloat16_rn(v.x - __bfloat162float(h01.x));           \
        l01.y = __float2bfloat16_rn(v.y - __bfloat162float(h01.y));           \
        l23.x = __float2bfloat16_rn(v.z - __bfloat162float(h23.x));           \
        l23.y = __float2bfloat16_rn(v.w - __bfloat162float(h23.y));           \
        ((__nv_bfloat162*)HI)[2 * i]     = h01;                               \
        ((__nv_bfloat162*)HI)[2 * i + 1] = h23;                               \
        ((__nv_bfloat162*)LO)[2 * i]     = l01;                               \
        ((__nv_bfloat162*)LO)[2 * i + 1] = l23;                               \
    }
        SPLIT_LOOP(W1, g_w1hi, g_w1lo, NEXP * HDIM * DIN)
        SPLIT_LOOP(W2, g_w2hi, g_w2lo, NEXP * CDIM * HDIM)
        SPLIT_LOOP(Wm, g_wmhi, g_wmlo, NEXP * TOUT * CDIM)
#undef SPLIT_LOOP
    }
}

// ---------------- kernel 2: fc1 (128x128 tile, cp.async) ----------------
__global__ __launch_bounds__(256, 2) void fc1_mma(const float* __restrict__ b1) {
    const int e   = blockIdx.z;
    const int cnt = g_cnt[e];
    const int m0  = blockIdx.x * 128;
    if (m0 >= cnt) return;
    const int n0  = blockIdx.y * 128;
    const int tid = threadIdx.x;

    extern __shared__ char dsm[];
    const uint32_t sb = smem_u32(dsm);

    const int arow = tid >> 1;
    int r = m0 + arow; if (r >= cnt) r = cnt - 1;
    const int tok = g_tok[e * NTOK + r];
    const __nv_bfloat16* aghi = g_xhi + (size_t)tok * DIN + (tid & 1) * 16;
    const __nv_bfloat16* aglo = g_xlo + (size_t)tok * DIN + (tid & 1) * 16;
    const int brow = tid >> 1;
    const __nv_bfloat16* bghi = g_w1hi + ((size_t)e * HDIM + n0 + brow) * DIN + (tid & 1) * 16;
    const __nv_bfloat16* bglo = g_w1lo + ((size_t)e * HDIM + n0 + brow) * DIN + (tid & 1) * 16;

    float acc[4][4][4] = {};
    run_mainloop_cp<DIN / 32, 128, 128>(sb, aghi, aglo, bghi, bglo, acc);

    const int lane = tid & 31, wid = tid >> 5;
    const int warp_m = wid & 1, warp_n = wid >> 1;
#pragma unroll
    for (int nf = 0; nf < 4; nf++) {
        const int n = n0 + warp_n * 32 + nf * 8 + 2 * (lane & 3);
        const float bb0 = b1[e * HDIM + n];
        const float bb1 = b1[e * HDIM + n + 1];
#pragma unroll
        for (int mf = 0; mf < 4; mf++)
#pragma unroll
            for (int hr = 0; hr < 2; hr++) {
                const int m = m0 + warp_m * 64 + mf * 16 + (lane >> 2) + hr * 8;
                if (m < cnt) {
                    const float h0 = fmaxf(acc[mf][nf][2 * hr + 0] + bb0, 0.f);
                    const float h1 = fmaxf(acc[mf][nf][2 * hr + 1] + bb1, 0.f);
                    split_store2(g_Hhi, g_Hlo, ((size_t)e * NTOK + m) * HDIM + n, h0, h1);
                }
            }
    }
}

// ---------------- kernel 3: fc2 (64x64 tile + gate, cp.async) ----------------
__global__ __launch_bounds__(256, 2) void fc2_mma(const float* __restrict__ b2) {
    const int e   = blockIdx.z;
    const int cnt = g_cnt[e];
    const int m0  = blockIdx.x * 64;
    if (m0 >= cnt) return;
    const int tid = threadIdx.x;

    extern __shared__ char dsm[];
    const uint32_t sb = smem_u32(dsm);

    const int arow = tid >> 2;
    const __nv_bfloat16* aghi = g_Hhi + ((size_t)e * NTOK + m0 + arow) * HDIM + (tid & 3) * 8;
    const __nv_bfloat16* aglo = g_Hlo + ((size_t)e * NTOK + m0 + arow) * HDIM + (tid & 3) * 8;
    const int brow = tid >> 2;
    const __nv_bfloat16* bghi = g_w2hi + ((size_t)e * CDIM + brow) * HDIM + (tid & 3) * 8;
    const __nv_bfloat16* bglo = g_w2lo + ((size_t)e * CDIM + brow) * HDIM + (tid & 3) * 8;

    float acc[2][2][4] = {};
    run_mainloop_cp<HDIM / 32, 64, 64>(sb, aghi, aglo, bghi, bglo, acc);

    const int lane = tid & 31, wid = tid >> 5;
    const int warp_m = wid & 1, warp_n = wid >> 1;
#pragma unroll
    for (int nf = 0; nf < 2; nf++) {
        const int n = warp_n * 16 + nf * 8 + 2 * (lane & 3);
        const float bb0 = b2[e * CDIM + n];
        const float bb1 = b2[e * CDIM + n + 1];
#pragma unroll
        for (int mf = 0; mf < 2; mf++)
#pragma unroll
            for (int hr = 0; hr < 2; hr++) {
                const int m = m0 + warp_m * 32 + mf * 16 + (lane >> 2) + hr * 8;
                if (m < cnt) {
                    const float g = g_gate[e * NTOK + m];
                    const float o0 = (acc[mf][nf][2 * hr + 0] + bb0) * g;
                    const float o1 = (acc[mf][nf][2 * hr + 1] + bb1) * g;
                    split_store2(g_Ohi, g_Olo, ((size_t)e * NTOK + m) * CDIM + n, o0, o1);
                }
            }
    }
}

// ---------------- kernel 4: combine (64x128 tile -> partial buffers) ----------------
__global__ __launch_bounds__(256, 2) void combine_mma() {
    const int e   = blockIdx.z;
    const int cnt = g_cnt[e];
    const int m0  = blockIdx.x * 64;
    if (m0 >= cnt) return;
    const int n0  = blockIdx.y * 128;
    const int tid = threadIdx.x;

    extern __shared__ char dsm[];
    const uint32_t sb = smem_u32(dsm);

    const int arow = tid >> 2;
    const __nv_bfloat16* aghi = g_Ohi + ((size_t)e * NTOK + m0 + arow) * CDIM + (tid & 3) * 8;
    const __nv_bfloat16* aglo = g_Olo + ((size_t)e * NTOK + m0 + arow) * CDIM + (tid & 3) * 8;
    const int brow = tid >> 1;
    const __nv_bfloat16* bghi = g_wmhi + ((size_t)e * TOUT + n0 + brow) * CDIM + (tid & 1) * 16;
    const __nv_bfloat16* bglo = g_wmlo + ((size_t)e * TOUT + n0 + brow) * CDIM + (tid & 1) * 16;

    float acc[2][4][4] = {};
    run_mainloop_cp<CDIM / 32, 64, 128>(sb, aghi, aglo, bghi, bglo, acc);

    const int lane = tid & 31, wid = tid >> 5;
    const int warp_m = wid & 1, warp_n = wid >> 1;
#pragma unroll
    for (int mf = 0; mf < 2; mf++)
#pragma unroll
        for (int hr = 0; hr < 2; hr++) {
            const int m = m0 + warp_m * 32 + mf * 16 + (lane >> 2) + hr * 8;
            if (m < cnt) {
                const int tok = g_tok[e * NTOK + m];
                const int k   = g_slot[e * NTOK + m];
                float* yr = g_part + ((size_t)k * NTOK + tok) * TOUT + n0;
#pragma unroll
                for (int nf = 0; nf < 4; nf++) {
                    const int n = warp_n * 32 + nf * 8 + 2 * (lane & 3);
                    float2 v;
                    v.x = acc[mf][nf][2 * hr + 0];
                    v.y = acc[mf][nf][2 * hr + 1];
                    *(float2*)(yr + n) = v;
                }
            }
        }
}

// ---------------- kernel 5: finish — y = p0 + p1, EPS fixup; reset g_cnt ----------------
__global__ void finish_kernel(float4* __restrict__ y) {
    if (blockIdx.x == 0 && threadIdx.x < NEXP) g_cnt[threadIdx.x] = 0;  // clean for next launch
    const int n = NTOK * TOUT / 4;
    const float4* p0 = (const float4*)g_part;
    const float4* p1 = (const float4*)(g_part + (size_t)NTOK * TOUT);
    for (int i = blockIdx.x * blockDim.x + threadIdx.x; i < n;
         i += gridDim.x * blockDim.x) {
        const float4 a = p0[i];
        const float4 b = p1[i];
        float4 v;
        v.x = a.x + b.x; v.y = a.y + b.y; v.z = a.z + b.z; v.w = a.w + b.w;
        if (v.x == 0.f) v.x = EPSV;
        if (v.y == 0.f) v.y = EPSV;
        if (v.z == 0.f) v.z = EPSV;
        if (v.w == 0.f) v.w = EPSV;
        y[i] = v;
    }
}

// ---------------- launch ----------------
extern "C" void kernel_launch(void* const* d_in, const int* in_sizes, int n_in,
                              void* d_out, int out_size) {
    const float* x  = (const float*)d_in[0];
    // d_in[1] = labels (int64) — unused by the reference computation
    const float* wg = (const float*)d_in[2];
    const float* W1 = (const float*)d_in[3];
    const float* b1 = (const float*)d_in[4];
    const float* W2 = (const float*)d_in[5];
    const float* b2 = (const float*)d_in[6];
    const float* Wm = (const float*)d_in[7];
    float* y = (float*)d_out;

    cudaFuncSetAttribute(fc1_mma,     cudaFuncAttributeMaxDynamicSharedMemorySize, SMEM_FC1);
    cudaFuncSetAttribute(fc2_mma,     cudaFuncAttributeMaxDynamicSharedMemorySize, SMEM_FC2);
    cudaFuncSetAttribute(combine_mma, cudaFuncAttributeMaxDynamicSharedMemorySize, SMEM_CMB);

    prep_kernel<<<NTOK / 8 + 512, 256>>>(x, wg, W1, W2, Wm);

    dim3 g1(NTOK / 128, HDIM / 128, NEXP);  // (64, 2, 8)
    fc1_mma<<<g1, 256, SMEM_FC1>>>(b1);

    dim3 g2(NTOK / 64, 1, NEXP);            // (128, 1, 8)
    fc2_mma<<<g2, 256, SMEM_FC2>>>(b2);

    dim3 g3(NTOK / 64, TOUT / 128, NEXP);   // (128, 4, 8)
    combine_mma<<<g3, 256, SMEM_CMB>>>();

    finish_kernel<<<512, 256>>>((float4*)y);
}

// round 12
// speedup vs baseline: 2.5843x; 1.0779x over previous
#include <cuda_runtime.h>
#include <cuda_bf16.h>
#include <math.h>
#include <stdint.h>

#define NTOK 8192
#define DIN  768
#define HDIM 256
#define NEXP 8
#define CDIM 64
#define TOUT 512
#define EPSV 2.2204460492503131e-16f

// ---------------- static device scratch (allocation-free rule) ----------------
__device__ int           g_cnt[NEXP];            // zeroed at end of previous launch
__device__ int           g_tok[NEXP * NTOK];
__device__ unsigned char g_slot[NEXP * NTOK];
__device__ float         g_gate[NEXP * NTOK];
__device__ float         g_part[2ull * NTOK * TOUT];

__device__ __nv_bfloat16 g_xhi[NTOK * DIN],        g_xlo[NTOK * DIN];
__device__ __nv_bfloat16 g_w1hi[NEXP * HDIM * DIN], g_w1lo[NEXP * HDIM * DIN];
__device__ __nv_bfloat16 g_w2hi[NEXP * CDIM * HDIM], g_w2lo[NEXP * CDIM * HDIM];
__device__ __nv_bfloat16 g_wmhi[NEXP * TOUT * CDIM], g_wmlo[NEXP * TOUT * CDIM];
__device__ __nv_bfloat16 g_Hhi[(size_t)NEXP * NTOK * HDIM], g_Hlo[(size_t)NEXP * NTOK * HDIM];

// ---------------- helpers ----------------
__device__ __forceinline__ uint32_t smem_u32(const void* p) {
    return (uint32_t)__cvta_generic_to_shared(p);
}
__device__ __forceinline__ void ldmx4(uint32_t* r, uint32_t addr) {
    asm volatile("ldmatrix.sync.aligned.m8n8.x4.shared.b16 {%0,%1,%2,%3}, [%4];\n"
                 : "=r"(r[0]), "=r"(r[1]), "=r"(r[2]), "=r"(r[3]) : "r"(addr));
}
__device__ __forceinline__ void mma16816(float* c, const uint32_t* a, uint32_t b0, uint32_t b1) {
    asm volatile(
        "mma.sync.aligned.m16n8k16.row.col.f32.bf16.bf16.f32 "
        "{%0,%1,%2,%3}, {%4,%5,%6,%7}, {%8,%9}, {%0,%1,%2,%3};\n"
        : "+f"(c[0]), "+f"(c[1]), "+f"(c[2]), "+f"(c[3])
        : "r"(a[0]), "r"(a[1]), "r"(a[2]), "r"(a[3]), "r"(b0), "r"(b1));
}
__device__ __forceinline__ void cp16(uint32_t dst, const void* src) {
    asm volatile("cp.async.cg.shared.global [%0], [%1], 16;" :: "r"(dst), "l"(src));
}
#define CP_COMMIT() asm volatile("cp.async.commit_group;" ::: "memory")
#define CP_WAIT0()  asm volatile("cp.async.wait_group 0;" ::: "memory")

__device__ __forceinline__ void split_store2(__nv_bfloat16* hi, __nv_bfloat16* lo,
                                             size_t off, float v0, float v1) {
    __nv_bfloat16 h0 = __float2bfloat16_rn(v0), h1 = __float2bfloat16_rn(v1);
    __nv_bfloat162 th; th.x = h0; th.y = h1;
    __nv_bfloat162 tl;
    tl.x = __float2bfloat16_rn(v0 - __bfloat162float(h0));
    tl.y = __float2bfloat16_rn(v1 - __bfloat162float(h1));
    *(__nv_bfloat162*)(hi + off) = th;
    *(__nv_bfloat162*)(lo + off) = tl;
}

// ---------------- smem geometry (row pitch 80B, conflict-free ldmatrix) ----------------
#define TSZ(R) ((R) * 80)
#define STG(BM, BN) (2 * TSZ(BM) + 2 * TSZ(BN))
#define SMEM_FC1 (2 * STG(128, 128))   // 81920
// fused fc2+combine: O_smem (2 splits x 64 rows x 144B) + B (2 chunks x 2 splits x 128 x 80)
#define OSM_PITCH 144
#define OSM_PLANE (64 * OSM_PITCH)     // 9216
#define F2C_B_OFF (2 * OSM_PLANE)      // 18432
#define SMEM_F2C  (F2C_B_OFF + 2 * 2 * TSZ(128))   // 18432 + 40960 = 59392

// ---------------- shared mainloop (cp.async double-buffered, 1 barrier/chunk) ----------------
// Block tile BM x BN x 32K, 8 warps as 2(M) x 4(N); per-warp tile (BM/2) x (BN/4).
// MMA order per accumulator: hh -> hl -> lh (bitwise-stable across tile shapes).
template <int NCH, int BM, int BN>
__device__ __forceinline__ void run_mainloop_cp(
    uint32_t sb,
    const __nv_bfloat16* aghi, const __nv_bfloat16* aglo,
    const __nv_bfloat16* bghi, const __nv_bfloat16* bglo,
    float (&acc)[BM / 32][BN / 32][4])
{
    constexpr int MF = BM / 32;
    constexpr int NF = BN / 32;
    constexpr int AS = TSZ(BM);
    constexpr int BS = TSZ(BN);
    constexpr int ST = STG(BM, BN);
    const int tid  = threadIdx.x;
    const int lane = tid & 31;
    const int wid  = tid >> 5;
    const int warp_m = wid & 1;
    const int warp_n = wid >> 1;

    const uint32_t a_off = (BM == 128) ? ((tid >> 1) * 80 + (tid & 1) * 32)
                                       : ((tid >> 2) * 80 + (tid & 3) * 16);
    const uint32_t b_off = (BN == 128) ? ((tid >> 1) * 80 + (tid & 1) * 32)
                                       : ((tid >> 2) * 80 + (tid & 3) * 16);

    const int ar = warp_m * (BM / 2) + ((lane >> 3) & 1) * 8 + (lane & 7);
    const int ac = (lane >> 4) * 8;
    const uint32_t la = sb + ar * 80 + ac * 2;
    const int br = warp_n * (BN / 4) + ((lane >> 4) << 3) + (lane & 7);
    const int bc = ((lane >> 3) & 1) * 8;
    const uint32_t lb = sb + 2 * AS + br * 80 + bc * 2;

    auto load_stage = [&](int s) {
        const uint32_t st = sb + s * ST;
        if (BM == 128) {
            cp16(st + a_off,           aghi);
            cp16(st + a_off + 16,      aghi + 8);
            cp16(st + AS + a_off,      aglo);
            cp16(st + AS + a_off + 16, aglo + 8);
        } else {
            cp16(st + a_off,      aghi);
            cp16(st + AS + a_off, aglo);
        }
        if (BN == 128) {
            cp16(st + 2 * AS + b_off,           bghi);
            cp16(st + 2 * AS + b_off + 16,      bghi + 8);
            cp16(st + 2 * AS + BS + b_off,      bglo);
            cp16(st + 2 * AS + BS + b_off + 16, bglo + 8);
        } else {
            cp16(st + 2 * AS + b_off,      bghi);
            cp16(st + 2 * AS + BS + b_off, bglo);
        }
        aghi += 32; aglo += 32; bghi += 32; bglo += 32;
    };

    load_stage(0);
    CP_COMMIT();

    for (int ch = 0; ch < NCH; ch++) {
        CP_WAIT0();
        __syncthreads();
        if (ch + 1 < NCH) {
            load_stage((ch + 1) & 1);
            CP_COMMIT();
        }

        const uint32_t sa  = la + (ch & 1) * ST;
        const uint32_t sbb = lb + (ch & 1) * ST;
#pragma unroll
        for (int kk = 0; kk < 2; kk++) {
            uint32_t bh[2 * NF], bl[2 * NF];
            ldmx4(bh, sbb + kk * 32);
            ldmx4(bl, sbb + BS + kk * 32);
            if (NF == 4) {
                ldmx4(bh + 4, sbb + 1280 + kk * 32);
                ldmx4(bl + 4, sbb + BS + 1280 + kk * 32);
            }
#pragma unroll
            for (int mf = 0; mf < MF; mf++) {
                uint32_t ah[4], al[4];
                ldmx4(ah, sa + (uint32_t)(mf * 1280) + kk * 32);
                ldmx4(al, sa + AS + (uint32_t)(mf * 1280) + kk * 32);
#pragma unroll
                for (int nf = 0; nf < NF; nf++)
                    mma16816(acc[mf][nf], ah, bh[2 * nf], bh[2 * nf + 1]);
#pragma unroll
                for (int nf = 0; nf < NF; nf++)
                    mma16816(acc[mf][nf], ah, bl[2 * nf], bl[2 * nf + 1]);
#pragma unroll
                for (int nf = 0; nf < NF; nf++)
                    mma16816(acc[mf][nf], al, bh[2 * nf], bh[2 * nf + 1]);
            }
        }
    }
}

// ---------------- kernel 1: prep = gating + x split ∥ weight split ----------------
__global__ __launch_bounds__(256) void prep_kernel(
    const float* __restrict__ x,  const float* __restrict__ wg,
    const float* __restrict__ W1, const float* __restrict__ W2,
    const float* __restrict__ Wm)
{
    if (blockIdx.x < NTOK / 8) {
        const int tok  = (blockIdx.x * blockDim.x + threadIdx.x) >> 5;
        const int lane = threadIdx.x & 31;
        const float* xr = x + (size_t)tok * DIN;
        __nv_bfloat16* xh = g_xhi + (size_t)tok * DIN;
        __nv_bfloat16* xl = g_xlo + (size_t)tok * DIN;

        float acc[8];
#pragma unroll
        for (int e = 0; e < 8; e++) acc[e] = 0.f;

#pragma unroll
        for (int it = 0; it < DIN / 32; it++) {
            const int d = it * 32 + lane;
            const float xv = xr[d];
            const __nv_bfloat16 h = __float2bfloat16_rn(xv);
            xh[d] = h;
            xl[d] = __float2bfloat16_rn(xv - __bfloat162float(h));
            const float4 w0 = *(const float4*)(wg + d * 8);
            const float4 w1 = *(const float4*)(wg + d * 8 + 4);
            acc[0] += xv * w0.x; acc[1] += xv * w0.y;
            acc[2] += xv * w0.z; acc[3] += xv * w0.w;
            acc[4] += xv * w1.x; acc[5] += xv * w1.y;
            acc[6] += xv * w1.z; acc[7] += xv * w1.w;
        }
#pragma unroll
        for (int e = 0; e < 8; e++)
#pragma unroll
            for (int off = 16; off; off >>= 1)
                acc[e] += __shfl_xor_sync(0xFFFFFFFFu, acc[e], off);

        if (lane == 0) {
            int i0 = 0; float v0 = acc[0];
#pragma unroll
            for (int e = 1; e < 8; e++) if (acc[e] > v0) { v0 = acc[e]; i0 = e; }
            int i1 = -1; float v1 = -3.4e38f;
#pragma unroll
            for (int e = 0; e < 8; e++)
                if (e != i0 && acc[e] > v1) { v1 = acc[e]; i1 = e; }
            const float tt = expf(v1 - v0);
            const float g0 = 1.f / (1.f + tt);
            const float g1 = tt / (1.f + tt);

            int s0 = atomicAdd(&g_cnt[i0], 1);
            g_tok[i0 * NTOK + s0]  = tok;
            g_slot[i0 * NTOK + s0] = 0;
            g_gate[i0 * NTOK + s0] = g0;
            int s1 = atomicAdd(&g_cnt[i1], 1);
            g_tok[i1 * NTOK + s1]  = tok;
            g_slot[i1 * NTOK + s1] = 1;
            g_gate[i1 * NTOK + s1] = g1;
        }
    } else {
        const int stride = 512 * 256;
        const int t = (blockIdx.x - NTOK / 8) * 256 + threadIdx.x;
#define SPLIT_LOOP(SRC, HI, LO, N)                                            \
    for (int i = t; i < (N) / 4; i += stride) {                               \
        const float4 v = ((const float4*)SRC)[i];                             \
        __nv_bfloat162 h01, h23, l01, l23;                                    \
        h01.x = __float2bfloat16_rn(v.x); h01.y = __float2bfloat16_rn(v.y);   \
        h23.x = __float2bfloat16_rn(v.z); h23.y = __float2bfloat16_rn(v.w);   \
        l01.x = __float2bfloat16_rn(v.x - __bfloat162float(h01.x));           \
        l01.y = __float2bfloat16_rn(v.y - __bfloat162float(h01.y));           \
        l23.x = __float2bfloat16_rn(v.z - __bfloat162float(h23.x));           \
        l23.y = __float2bfloat16_rn(v.w - __bfloat162float(h23.y));           \
        ((__nv_bfloat162*)HI)[2 * i]     = h01;                               \
        ((__nv_bfloat162*)HI)[2 * i + 1] = h23;                               \
        ((__nv_bfloat162*)LO)[2 * i]     = l01;                               \
        ((__nv_bfloat162*)LO)[2 * i + 1] = l23;                               \
    }
        SPLIT_LOOP(W1, g_w1hi, g_w1lo, NEXP * HDIM * DIN)
        SPLIT_LOOP(W2, g_w2hi, g_w2lo, NEXP * CDIM * HDIM)
        SPLIT_LOOP(Wm, g_wmhi, g_wmlo, NEXP * TOUT * CDIM)
#undef SPLIT_LOOP
    }
}

// ---------------- kernel 2: fc1 (128x128 tile, cp.async) ----------------
__global__ __launch_bounds__(256, 2) void fc1_mma(const float* __restrict__ b1) {
    const int e   = blockIdx.z;
    const int cnt = g_cnt[e];
    const int m0  = blockIdx.x * 128;
    if (m0 >= cnt) return;
    const int n0  = blockIdx.y * 128;
    const int tid = threadIdx.x;

    extern __shared__ char dsm[];
    const uint32_t sb = smem_u32(dsm);

    const int arow = tid >> 1;
    int r = m0 + arow; if (r >= cnt) r = cnt - 1;
    const int tok = g_tok[e * NTOK + r];
    const __nv_bfloat16* aghi = g_xhi + (size_t)tok * DIN + (tid & 1) * 16;
    const __nv_bfloat16* aglo = g_xlo + (size_t)tok * DIN + (tid & 1) * 16;
    const int brow = tid >> 1;
    const __nv_bfloat16* bghi = g_w1hi + ((size_t)e * HDIM + n0 + brow) * DIN + (tid & 1) * 16;
    const __nv_bfloat16* bglo = g_w1lo + ((size_t)e * HDIM + n0 + brow) * DIN + (tid & 1) * 16;

    float acc[4][4][4] = {};
    run_mainloop_cp<DIN / 32, 128, 128>(sb, aghi, aglo, bghi, bglo, acc);

    const int lane = tid & 31, wid = tid >> 5;
    const int warp_m = wid & 1, warp_n = wid >> 1;
#pragma unroll
    for (int nf = 0; nf < 4; nf++) {
        const int n = n0 + warp_n * 32 + nf * 8 + 2 * (lane & 3);
        const float bb0 = b1[e * HDIM + n];
        const float bb1 = b1[e * HDIM + n + 1];
#pragma unroll
        for (int mf = 0; mf < 4; mf++)
#pragma unroll
            for (int hr = 0; hr < 2; hr++) {
                const int m = m0 + warp_m * 64 + mf * 16 + (lane >> 2) + hr * 8;
                if (m < cnt) {
                    const float h0 = fmaxf(acc[mf][nf][2 * hr + 0] + bb0, 0.f);
                    const float h1 = fmaxf(acc[mf][nf][2 * hr + 1] + bb1, 0.f);
                    split_store2(g_Hhi, g_Hlo, ((size_t)e * NTOK + m) * HDIM + n, h0, h1);
                }
            }
    }
}

// ---------------- kernel 3: fused fc2 + combine ----------------
// Phase 1: fc2 64x64x256 tile -> gate-scaled O split hi/lo into smem.
// Phase 2: for each of 4 Wm subtiles (BN=128, K=64), MMA from smem O, store partials.
__global__ __launch_bounds__(256, 2) void fc2cmb_mma(const float* __restrict__ b2) {
    const int e   = blockIdx.z;
    const int cnt = g_cnt[e];
    const int m0  = blockIdx.x * 64;
    if (m0 >= cnt) return;
    const int tid = threadIdx.x, lane = tid & 31, wid = tid >> 5;
    const int warp_m = wid & 1, warp_n = wid >> 1;

    extern __shared__ char dsm[];
    const uint32_t sb = smem_u32(dsm);

    // ---- phase 1: fc2 mainloop (identical math/order to previous fc2_mma) ----
    {
        const int arow = tid >> 2;
        const __nv_bfloat16* aghi = g_Hhi + ((size_t)e * NTOK + m0 + arow) * HDIM + (tid & 3) * 8;
        const __nv_bfloat16* aglo = g_Hlo + ((size_t)e * NTOK + m0 + arow) * HDIM + (tid & 3) * 8;
        const int brow = tid >> 2;
        const __nv_bfloat16* bghi = g_w2hi + ((size_t)e * CDIM + brow) * HDIM + (tid & 3) * 8;
        const __nv_bfloat16* bglo = g_w2lo + ((size_t)e * CDIM + brow) * HDIM + (tid & 3) * 8;

        float acc1[2][2][4] = {};
        run_mainloop_cp<HDIM / 32, 64, 64>(sb, aghi, aglo, bghi, bglo, acc1);
        __syncthreads();   // stage-buffer reads done before O_smem overwrites them

        // epilogue: O = (acc + b2) * gate, split hi/lo -> smem (pitch 144)
#pragma unroll
        for (int nf = 0; nf < 2; nf++) {
            const int n = warp_n * 16 + nf * 8 + 2 * (lane & 3);
            const float bb0 = b2[e * CDIM + n];
            const float bb1 = b2[e * CDIM + n + 1];
#pragma unroll
            for (int mf = 0; mf < 2; mf++)
#pragma unroll
                for (int hr = 0; hr < 2; hr++) {
                    const int ml = warp_m * 32 + mf * 16 + (lane >> 2) + hr * 8;
                    const int m  = m0 + ml;
                    const float g = (m < cnt) ? g_gate[e * NTOK + m] : 0.f;
                    const float o0 = (acc1[mf][nf][2 * hr + 0] + bb0) * g;
                    const float o1 = (acc1[mf][nf][2 * hr + 1] + bb1) * g;
                    __nv_bfloat16 h0 = __float2bfloat16_rn(o0), h1 = __float2bfloat16_rn(o1);
                    __nv_bfloat162 th; th.x = h0; th.y = h1;
                    __nv_bfloat162 tl;
                    tl.x = __float2bfloat16_rn(o0 - __bfloat162float(h0));
                    tl.y = __float2bfloat16_rn(o1 - __bfloat162float(h1));
                    *(__nv_bfloat162*)(dsm + ml * OSM_PITCH + n * 2) = th;
                    *(__nv_bfloat162*)(dsm + OSM_PLANE + ml * OSM_PITCH + n * 2) = tl;
                }
        }
        __syncthreads();
    }

    // ---- phase 2: combine over 4 Wm subtiles (BN=128, K=64 = 2 chunks) ----
    const int brow2 = tid >> 1, bhf = tid & 1;
    const __nv_bfloat16* wmh = g_wmhi + ((size_t)e * TOUT + brow2) * CDIM + bhf * 16;
    const __nv_bfloat16* wml = g_wmlo + ((size_t)e * TOUT + brow2) * CDIM + bhf * 16;
    const uint32_t bo = (uint32_t)(brow2 * 80 + bhf * 32);

    const int ar2 = warp_m * 32 + ((lane >> 3) & 1) * 8 + (lane & 7);
    const uint32_t la2 = sb + ar2 * OSM_PITCH + ((lane >> 4) * 8) * 2;
    const int br2 = warp_n * 32 + ((lane >> 4) << 3) + (lane & 7);
    const uint32_t lb2 = sb + F2C_B_OFF + br2 * 80 + (((lane >> 3) & 1) * 8) * 2;

    // precompute row bookkeeping
    int mrow[2][2], tokr[2][2], slotr[2][2];
#pragma unroll
    for (int mf = 0; mf < 2; mf++)
#pragma unroll
        for (int hr = 0; hr < 2; hr++) {
            const int m = m0 + warp_m * 32 + mf * 16 + (lane >> 2) + hr * 8;
            mrow[mf][hr] = m;
            tokr[mf][hr] = (m < cnt) ? g_tok[e * NTOK + m] : 0;
            slotr[mf][hr] = (m < cnt) ? g_slot[e * NTOK + m] : 0;
        }

    for (int s = 0; s < 4; s++) {
        const int n0 = s * 128;
        // load B (both chunks, both splits) into smem
#pragma unroll
        for (int c = 0; c < 2; c++) {
            const __nv_bfloat16* sh = wmh + (size_t)n0 * CDIM + c * 32;
            const __nv_bfloat16* sl = wml + (size_t)n0 * CDIM + c * 32;
            const uint32_t dst = sb + F2C_B_OFF + c * 20480;
            cp16(dst + bo,              sh);
            cp16(dst + bo + 16,         sh + 8);
            cp16(dst + 10240 + bo,      sl);
            cp16(dst + 10240 + bo + 16, sl + 8);
        }
        CP_COMMIT(); CP_WAIT0();
        __syncthreads();

        float acc2[2][4][4] = {};
#pragma unroll
        for (int ch = 0; ch < 2; ch++) {
#pragma unroll
            for (int kk = 0; kk < 2; kk++) {
                uint32_t bh[8], bl[8];
                ldmx4(bh,     lb2 + ch * 20480 + kk * 32);
                ldmx4(bh + 4, lb2 + ch * 20480 + 1280 + kk * 32);
                ldmx4(bl,     lb2 + ch * 20480 + 10240 + kk * 32);
                ldmx4(bl + 4, lb2 + ch * 20480 + 10240 + 1280 + kk * 32);
#pragma unroll
                for (int mf = 0; mf < 2; mf++) {
                    uint32_t ah[4], al[4];
                    ldmx4(ah, la2 + (uint32_t)(mf * 16 * OSM_PITCH) + ch * 64 + kk * 32);
                    ldmx4(al, la2 + OSM_PLANE + (uint32_t)(mf * 16 * OSM_PITCH) + ch * 64 + kk * 32);
#pragma unroll
                    for (int nf = 0; nf < 4; nf++)
                        mma16816(acc2[mf][nf], ah, bh[2 * nf], bh[2 * nf + 1]);
#pragma unroll
                    for (int nf = 0; nf < 4; nf++)
                        mma16816(acc2[mf][nf], ah, bl[2 * nf], bl[2 * nf + 1]);
#pragma unroll
                    for (int nf = 0; nf < 4; nf++)
                        mma16816(acc2[mf][nf], al, bh[2 * nf], bh[2 * nf + 1]);
                }
            }
        }

        // epilogue: partial stores (same mapping/values as previous combine_mma)
#pragma unroll
        for (int mf = 0; mf < 2; mf++)
#pragma unroll
            for (int hr = 0; hr < 2; hr++) {
                if (mrow[mf][hr] < cnt) {
                    float* yr = g_part + ((size_t)slotr[mf][hr] * NTOK + tokr[mf][hr]) * TOUT + n0;
#pragma unroll
                    for (int nf = 0; nf < 4; nf++) {
                        const int n = warp_n * 32 + nf * 8 + 2 * (lane & 3);
                        float2 v;
                        v.x = acc2[mf][nf][2 * hr + 0];
                        v.y = acc2[mf][nf][2 * hr + 1];
                        *(float2*)(yr + n) = v;
                    }
                }
            }
        __syncthreads();   // before next subtile's B overwrite
    }
}

// ---------------- kernel 5: finish — y = p0 + p1, EPS fixup; reset g_cnt ----------------
__global__ void finish_kernel(float4* __restrict__ y) {
    if (blockIdx.x == 0 && threadIdx.x < NEXP) g_cnt[threadIdx.x] = 0;  // clean for next launch
    const int n = NTOK * TOUT / 4;
    const float4* p0 = (const float4*)g_part;
    const float4* p1 = (const float4*)(g_part + (size_t)NTOK * TOUT);
    for (int i = blockIdx.x * blockDim.x + threadIdx.x; i < n;
         i += gridDim.x * blockDim.x) {
        const float4 a = p0[i];
        const float4 b = p1[i];
        float4 v;
        v.x = a.x + b.x; v.y = a.y + b.y; v.z = a.z + b.z; v.w = a.w + b.w;
        if (v.x == 0.f) v.x = EPSV;
        if (v.y == 0.f) v.y = EPSV;
        if (v.z == 0.f) v.z = EPSV;
        if (v.w == 0.f) v.w = EPSV;
        y[i] = v;
    }
}

// ---------------- launch ----------------
extern "C" void kernel_launch(void* const* d_in, const int* in_sizes, int n_in,
                              void* d_out, int out_size) {
    const float* x  = (const float*)d_in[0];
    // d_in[1] = labels (int64) — unused by the reference computation
    const float* wg = (const float*)d_in[2];
    const float* W1 = (const float*)d_in[3];
    const float* b1 = (const float*)d_in[4];
    const float* W2 = (const float*)d_in[5];
    const float* b2 = (const float*)d_in[6];
    const float* Wm = (const float*)d_in[7];
    float* y = (float*)d_out;

    cudaFuncSetAttribute(fc1_mma,    cudaFuncAttributeMaxDynamicSharedMemorySize, SMEM_FC1);
    cudaFuncSetAttribute(fc2cmb_mma, cudaFuncAttributeMaxDynamicSharedMemorySize, SMEM_F2C);

    prep_kernel<<<NTOK / 8 + 512, 256>>>(x, wg, W1, W2, Wm);

    dim3 g1(NTOK / 128, HDIM / 128, NEXP);  // (64, 2, 8)
    fc1_mma<<<g1, 256, SMEM_FC1>>>(b1);

    dim3 g2(NTOK / 64, 1, NEXP);            // (128, 1, 8)
    fc2cmb_mma<<<g2, 256, SMEM_F2C>>>(b2);

    finish_kernel<<<512, 256>>>((float4*)y);
}

// round 13
// speedup vs baseline: 2.6060x; 1.0084x over previous
#include <cuda_runtime.h>
#include <cuda_bf16.h>
#include <math.h>
#include <stdint.h>

#define NTOK 8192
#define DIN  768
#define HDIM 256
#define NEXP 8
#define CDIM 64
#define TOUT 512
#define EPSV 2.2204460492503131e-16f

// ---------------- static device scratch (allocation-free rule) ----------------
__device__ int           g_cnt[NEXP];            // zeroed at end of previous launch
__device__ int           g_tok[NEXP * NTOK];
__device__ unsigned char g_slot[NEXP * NTOK];
__device__ float         g_gate[NEXP * NTOK];
__device__ float         g_part[2ull * NTOK * TOUT];

__device__ __nv_bfloat16 g_xhi[NTOK * DIN],        g_xlo[NTOK * DIN];
__device__ __nv_bfloat16 g_w1hi[NEXP * HDIM * DIN], g_w1lo[NEXP * HDIM * DIN];
__device__ __nv_bfloat16 g_w2hi[NEXP * CDIM * HDIM], g_w2lo[NEXP * CDIM * HDIM];
__device__ __nv_bfloat16 g_wmhi[NEXP * TOUT * CDIM], g_wmlo[NEXP * TOUT * CDIM];
__device__ __nv_bfloat16 g_Hhi[(size_t)NEXP * NTOK * HDIM], g_Hlo[(size_t)NEXP * NTOK * HDIM];

// ---------------- helpers ----------------
__device__ __forceinline__ uint32_t smem_u32(const void* p) {
    return (uint32_t)__cvta_generic_to_shared(p);
}
__device__ __forceinline__ void ldmx4(uint32_t* r, uint32_t addr) {
    asm volatile("ldmatrix.sync.aligned.m8n8.x4.shared.b16 {%0,%1,%2,%3}, [%4];\n"
                 : "=r"(r[0]), "=r"(r[1]), "=r"(r[2]), "=r"(r[3]) : "r"(addr));
}
__device__ __forceinline__ void mma16816(float* c, const uint32_t* a, uint32_t b0, uint32_t b1) {
    asm volatile(
        "mma.sync.aligned.m16n8k16.row.col.f32.bf16.bf16.f32 "
        "{%0,%1,%2,%3}, {%4,%5,%6,%7}, {%8,%9}, {%0,%1,%2,%3};\n"
        : "+f"(c[0]), "+f"(c[1]), "+f"(c[2]), "+f"(c[3])
        : "r"(a[0]), "r"(a[1]), "r"(a[2]), "r"(a[3]), "r"(b0), "r"(b1));
}
__device__ __forceinline__ void cp16(uint32_t dst, const void* src) {
    asm volatile("cp.async.cg.shared.global [%0], [%1], 16;" :: "r"(dst), "l"(src));
}
#define CP_COMMIT() asm volatile("cp.async.commit_group;" ::: "memory")
#define CP_WAIT0()  asm volatile("cp.async.wait_group 0;" ::: "memory")

__device__ __forceinline__ void split_store2(__nv_bfloat16* hi, __nv_bfloat16* lo,
                                             size_t off, float v0, float v1) {
    __nv_bfloat16 h0 = __float2bfloat16_rn(v0), h1 = __float2bfloat16_rn(v1);
    __nv_bfloat162 th; th.x = h0; th.y = h1;
    __nv_bfloat162 tl;
    tl.x = __float2bfloat16_rn(v0 - __bfloat162float(h0));
    tl.y = __float2bfloat16_rn(v1 - __bfloat162float(h1));
    *(__nv_bfloat162*)(hi + off) = th;
    *(__nv_bfloat162*)(lo + off) = tl;
}

// ---------------- smem geometry (row pitch 80B, conflict-free ldmatrix) ----------------
#define TSZ(R) ((R) * 80)
#define STG(BM, BN) (2 * TSZ(BM) + 2 * TSZ(BN))
#define SMEM_FC1 (2 * STG(128, 128))   // 81920
// fused fc2+combine layout:
//   P (phase-1 staging, 2 stages of STG(64,64)) : [0, 40960)
//   O (2 splits x 64 rows x 144B)               : [40960, 59392)
//   B (one Wm subtile: 2 chunks x 2 splits)     : [59392, 100352)
// Phase 2 ping-pongs subtile B buffers between regions B and P.
#define OSM_PITCH 144
#define OSM_PLANE (64 * OSM_PITCH)     // 9216
#define F2C_P_OFF 0
#define F2C_O_OFF 40960
#define F2C_B_OFF 59392
#define F2C_BUFSZ 40960
#define SMEM_F2C  (F2C_B_OFF + F2C_BUFSZ)   // 100352

// ---------------- shared mainloop (cp.async double-buffered, 1 barrier/chunk) ----------------
// Block tile BM x BN x 32K, 8 warps as 2(M) x 4(N); per-warp tile (BM/2) x (BN/4).
// MMA order per accumulator: hh -> hl -> lh (bitwise-stable across tile shapes).
template <int NCH, int BM, int BN>
__device__ __forceinline__ void run_mainloop_cp(
    uint32_t sb,
    const __nv_bfloat16* aghi, const __nv_bfloat16* aglo,
    const __nv_bfloat16* bghi, const __nv_bfloat16* bglo,
    float (&acc)[BM / 32][BN / 32][4])
{
    constexpr int MF = BM / 32;
    constexpr int NF = BN / 32;
    constexpr int AS = TSZ(BM);
    constexpr int BS = TSZ(BN);
    constexpr int ST = STG(BM, BN);
    const int tid  = threadIdx.x;
    const int lane = tid & 31;
    const int wid  = tid >> 5;
    const int warp_m = wid & 1;
    const int warp_n = wid >> 1;

    const uint32_t a_off = (BM == 128) ? ((tid >> 1) * 80 + (tid & 1) * 32)
                                       : ((tid >> 2) * 80 + (tid & 3) * 16);
    const uint32_t b_off = (BN == 128) ? ((tid >> 1) * 80 + (tid & 1) * 32)
                                       : ((tid >> 2) * 80 + (tid & 3) * 16);

    const int ar = warp_m * (BM / 2) + ((lane >> 3) & 1) * 8 + (lane & 7);
    const int ac = (lane >> 4) * 8;
    const uint32_t la = sb + ar * 80 + ac * 2;
    const int br = warp_n * (BN / 4) + ((lane >> 4) << 3) + (lane & 7);
    const int bc = ((lane >> 3) & 1) * 8;
    const uint32_t lb = sb + 2 * AS + br * 80 + bc * 2;

    auto load_stage = [&](int s) {
        const uint32_t st = sb + s * ST;
        if (BM == 128) {
            cp16(st + a_off,           aghi);
            cp16(st + a_off + 16,      aghi + 8);
            cp16(st + AS + a_off,      aglo);
            cp16(st + AS + a_off + 16, aglo + 8);
        } else {
            cp16(st + a_off,      aghi);
            cp16(st + AS + a_off, aglo);
        }
        if (BN == 128) {
            cp16(st + 2 * AS + b_off,           bghi);
            cp16(st + 2 * AS + b_off + 16,      bghi + 8);
            cp16(st + 2 * AS + BS + b_off,      bglo);
            cp16(st + 2 * AS + BS + b_off + 16, bglo + 8);
        } else {
            cp16(st + 2 * AS + b_off,      bghi);
            cp16(st + 2 * AS + BS + b_off, bglo);
        }
        aghi += 32; aglo += 32; bghi += 32; bglo += 32;
    };

    load_stage(0);
    CP_COMMIT();

    for (int ch = 0; ch < NCH; ch++) {
        CP_WAIT0();
        __syncthreads();
        if (ch + 1 < NCH) {
            load_stage((ch + 1) & 1);
            CP_COMMIT();
        }

        const uint32_t sa  = la + (ch & 1) * ST;
        const uint32_t sbb = lb + (ch & 1) * ST;
#pragma unroll
        for (int kk = 0; kk < 2; kk++) {
            uint32_t bh[2 * NF], bl[2 * NF];
            ldmx4(bh, sbb + kk * 32);
            ldmx4(bl, sbb + BS + kk * 32);
            if (NF == 4) {
                ldmx4(bh + 4, sbb + 1280 + kk * 32);
                ldmx4(bl + 4, sbb + BS + 1280 + kk * 32);
            }
#pragma unroll
            for (int mf = 0; mf < MF; mf++) {
                uint32_t ah[4], al[4];
                ldmx4(ah, sa + (uint32_t)(mf * 1280) + kk * 32);
                ldmx4(al, sa + AS + (uint32_t)(mf * 1280) + kk * 32);
#pragma unroll
                for (int nf = 0; nf < NF; nf++)
                    mma16816(acc[mf][nf], ah, bh[2 * nf], bh[2 * nf + 1]);
#pragma unroll
                for (int nf = 0; nf < NF; nf++)
                    mma16816(acc[mf][nf], ah, bl[2 * nf], bl[2 * nf + 1]);
#pragma unroll
                for (int nf = 0; nf < NF; nf++)
                    mma16816(acc[mf][nf], al, bh[2 * nf], bh[2 * nf + 1]);
            }
        }
    }
}

// ---------------- kernel 1: prep = gating + x split ∥ weight split ----------------
__global__ __launch_bounds__(256) void prep_kernel(
    const float* __restrict__ x,  const float* __restrict__ wg,
    const float* __restrict__ W1, const float* __restrict__ W2,
    const float* __restrict__ Wm)
{
    if (blockIdx.x < NTOK / 8) {
        const int tok  = (blockIdx.x * blockDim.x + threadIdx.x) >> 5;
        const int lane = threadIdx.x & 31;
        const float* xr = x + (size_t)tok * DIN;
        __nv_bfloat16* xh = g_xhi + (size_t)tok * DIN;
        __nv_bfloat16* xl = g_xlo + (size_t)tok * DIN;

        float acc[8];
#pragma unroll
        for (int e = 0; e < 8; e++) acc[e] = 0.f;

#pragma unroll
        for (int it = 0; it < DIN / 32; it++) {
            const int d = it * 32 + lane;
            const float xv = xr[d];
            const __nv_bfloat16 h = __float2bfloat16_rn(xv);
            xh[d] = h;
            xl[d] = __float2bfloat16_rn(xv - __bfloat162float(h));
            const float4 w0 = *(const float4*)(wg + d * 8);
            const float4 w1 = *(const float4*)(wg + d * 8 + 4);
            acc[0] += xv * w0.x; acc[1] += xv * w0.y;
            acc[2] += xv * w0.z; acc[3] += xv * w0.w;
            acc[4] += xv * w1.x; acc[5] += xv * w1.y;
            acc[6] += xv * w1.z; acc[7] += xv * w1.w;
        }
#pragma unroll
        for (int e = 0; e < 8; e++)
#pragma unroll
            for (int off = 16; off; off >>= 1)
                acc[e] += __shfl_xor_sync(0xFFFFFFFFu, acc[e], off);

        if (lane == 0) {
            int i0 = 0; float v0 = acc[0];
#pragma unroll
            for (int e = 1; e < 8; e++) if (acc[e] > v0) { v0 = acc[e]; i0 = e; }
            int i1 = -1; float v1 = -3.4e38f;
#pragma unroll
            for (int e = 0; e < 8; e++)
                if (e != i0 && acc[e] > v1) { v1 = acc[e]; i1 = e; }
            const float tt = expf(v1 - v0);
            const float g0 = 1.f / (1.f + tt);
            const float g1 = tt / (1.f + tt);

            int s0 = atomicAdd(&g_cnt[i0], 1);
            g_tok[i0 * NTOK + s0]  = tok;
            g_slot[i0 * NTOK + s0] = 0;
            g_gate[i0 * NTOK + s0] = g0;
            int s1 = atomicAdd(&g_cnt[i1], 1);
            g_tok[i1 * NTOK + s1]  = tok;
            g_slot[i1 * NTOK + s1] = 1;
            g_gate[i1 * NTOK + s1] = g1;
        }
    } else {
        const int stride = 512 * 256;
        const int t = (blockIdx.x - NTOK / 8) * 256 + threadIdx.x;
#define SPLIT_LOOP(SRC, HI, LO, N)                                            \
    for (int i = t; i < (N) / 4; i += stride) {                               \
        const float4 v = ((const float4*)SRC)[i];                             \
        __nv_bfloat162 h01, h23, l01, l23;                                    \
        h01.x = __float2bfloat16_rn(v.x); h01.y = __float2bfloat16_rn(v.y);   \
        h23.x = __float2bfloat16_rn(v.z); h23.y = __float2bfloat16_rn(v.w);   \
        l01.x = __float2bfloat16_rn(v.x - __bfloat162float(h01.x));           \
        l01.y = __float2bfloat16_rn(v.y - __bfloat162float(h01.y));           \
        l23.x = __float2bfloat16_rn(v.z - __bfloat162float(h23.x));           \
        l23.y = __float2bfloat16_rn(v.w - __bfloat162float(h23.y));           \
        ((__nv_bfloat162*)HI)[2 * i]     = h01;                               \
        ((__nv_bfloat162*)HI)[2 * i + 1] = h23;                               \
        ((__nv_bfloat162*)LO)[2 * i]     = l01;                               \
        ((__nv_bfloat162*)LO)[2 * i + 1] = l23;                               \
    }
        SPLIT_LOOP(W1, g_w1hi, g_w1lo, NEXP * HDIM * DIN)
        SPLIT_LOOP(W2, g_w2hi, g_w2lo, NEXP * CDIM * HDIM)
        SPLIT_LOOP(Wm, g_wmhi, g_wmlo, NEXP * TOUT * CDIM)
#undef SPLIT_LOOP
    }
}

// ---------------- kernel 2: fc1 (128x128 tile, cp.async) ----------------
__global__ __launch_bounds__(256, 2) void fc1_mma(const float* __restrict__ b1) {
    const int e   = blockIdx.z;
    const int cnt = g_cnt[e];
    const int m0  = blockIdx.x * 128;
    if (m0 >= cnt) return;
    const int n0  = blockIdx.y * 128;
    const int tid = threadIdx.x;

    extern __shared__ char dsm[];
    const uint32_t sb = smem_u32(dsm);

    const int arow = tid >> 1;
    int r = m0 + arow; if (r >= cnt) r = cnt - 1;
    const int tok = g_tok[e * NTOK + r];
    const __nv_bfloat16* aghi = g_xhi + (size_t)tok * DIN + (tid & 1) * 16;
    const __nv_bfloat16* aglo = g_xlo + (size_t)tok * DIN + (tid & 1) * 16;
    const int brow = tid >> 1;
    const __nv_bfloat16* bghi = g_w1hi + ((size_t)e * HDIM + n0 + brow) * DIN + (tid & 1) * 16;
    const __nv_bfloat16* bglo = g_w1lo + ((size_t)e * HDIM + n0 + brow) * DIN + (tid & 1) * 16;

    float acc[4][4][4] = {};
    run_mainloop_cp<DIN / 32, 128, 128>(sb, aghi, aglo, bghi, bglo, acc);

    const int lane = tid & 31, wid = tid >> 5;
    const int warp_m = wid & 1, warp_n = wid >> 1;
#pragma unroll
    for (int nf = 0; nf < 4; nf++) {
        const int n = n0 + warp_n * 32 + nf * 8 + 2 * (lane & 3);
        const float bb0 = b1[e * HDIM + n];
        const float bb1 = b1[e * HDIM + n + 1];
#pragma unroll
        for (int mf = 0; mf < 4; mf++)
#pragma unroll
            for (int hr = 0; hr < 2; hr++) {
                const int m = m0 + warp_m * 64 + mf * 16 + (lane >> 2) + hr * 8;
                if (m < cnt) {
                    const float h0 = fmaxf(acc[mf][nf][2 * hr + 0] + bb0, 0.f);
                    const float h1 = fmaxf(acc[mf][nf][2 * hr + 1] + bb1, 0.f);
                    split_store2(g_Hhi, g_Hlo, ((size_t)e * NTOK + m) * HDIM + n, h0, h1);
                }
            }
    }
}

// ---------------- kernel 3: fused fc2 + combine (pipelined Wm prefetch) ----------------
// Phase 1: fc2 64x64x256 tile -> gate-scaled O split hi/lo into smem region O.
// Phase 2: 4 Wm subtiles (BN=128, K=64); B buffers ping-pong between regions B and P,
//          prefetched one subtile ahead (subtile 0 prefetched at kernel entry).
__global__ __launch_bounds__(256, 2) void fc2cmb_mma(const float* __restrict__ b2) {
    const int e   = blockIdx.z;
    const int cnt = g_cnt[e];
    const int m0  = blockIdx.x * 64;
    if (m0 >= cnt) return;
    const int tid = threadIdx.x, lane = tid & 31, wid = tid >> 5;
    const int warp_m = wid & 1, warp_n = wid >> 1;

    extern __shared__ char dsm[];
    const uint32_t sb = smem_u32(dsm);

    // ---- Wm producer mapping (per-thread) ----
    const int brow2 = tid >> 1, bhf = tid & 1;
    const __nv_bfloat16* wmh = g_wmhi + ((size_t)e * TOUT + brow2) * CDIM + bhf * 16;
    const __nv_bfloat16* wml = g_wmlo + ((size_t)e * TOUT + brow2) * CDIM + bhf * 16;
    const uint32_t bo = (uint32_t)(brow2 * 80 + bhf * 32);

    auto load_wm = [&](int s, uint32_t buf) {
        const int n0 = s * 128;
#pragma unroll
        for (int c = 0; c < 2; c++) {
            const __nv_bfloat16* sh = wmh + (size_t)n0 * CDIM + c * 32;
            const __nv_bfloat16* sl = wml + (size_t)n0 * CDIM + c * 32;
            const uint32_t dst = buf + c * 20480;
            cp16(dst + bo,              sh);
            cp16(dst + bo + 16,         sh + 8);
            cp16(dst + 10240 + bo,      sl);
            cp16(dst + 10240 + bo + 16, sl + 8);
        }
    };

    // prefetch subtile 0 into region B — independent of phase 1, hides its load
    load_wm(0, sb + F2C_B_OFF);
    CP_COMMIT();

    // ---- phase 1: fc2 mainloop (identical math/order) ----
    {
        const int arow = tid >> 2;
        const __nv_bfloat16* aghi = g_Hhi + ((size_t)e * NTOK + m0 + arow) * HDIM + (tid & 3) * 8;
        const __nv_bfloat16* aglo = g_Hlo + ((size_t)e * NTOK + m0 + arow) * HDIM + (tid & 3) * 8;
        const int brow = tid >> 2;
        const __nv_bfloat16* bghi = g_w2hi + ((size_t)e * CDIM + brow) * HDIM + (tid & 3) * 8;
        const __nv_bfloat16* bglo = g_w2lo + ((size_t)e * CDIM + brow) * HDIM + (tid & 3) * 8;

        float acc1[2][2][4] = {};
        run_mainloop_cp<HDIM / 32, 64, 64>(sb, aghi, aglo, bghi, bglo, acc1);

        // epilogue: O = (acc + b2) * gate, split hi/lo -> region O (pitch 144)
#pragma unroll
        for (int nf = 0; nf < 2; nf++) {
            const int n = warp_n * 16 + nf * 8 + 2 * (lane & 3);
            const float bb0 = b2[e * CDIM + n];
            const float bb1 = b2[e * CDIM + n + 1];
#pragma unroll
            for (int mf = 0; mf < 2; mf++)
#pragma unroll
                for (int hr = 0; hr < 2; hr++) {
                    const int ml = warp_m * 32 + mf * 16 + (lane >> 2) + hr * 8;
                    const int m  = m0 + ml;
                    const float g = (m < cnt) ? g_gate[e * NTOK + m] : 0.f;
                    const float o0 = (acc1[mf][nf][2 * hr + 0] + bb0) * g;
                    const float o1 = (acc1[mf][nf][2 * hr + 1] + bb1) * g;
                    __nv_bfloat16 h0 = __float2bfloat16_rn(o0), h1 = __float2bfloat16_rn(o1);
                    __nv_bfloat162 th; th.x = h0; th.y = h1;
                    __nv_bfloat162 tl;
                    tl.x = __float2bfloat16_rn(o0 - __bfloat162float(h0));
                    tl.y = __float2bfloat16_rn(o1 - __bfloat162float(h1));
                    *(__nv_bfloat162*)(dsm + F2C_O_OFF + ml * OSM_PITCH + n * 2) = th;
                    *(__nv_bfloat162*)(dsm + F2C_O_OFF + OSM_PLANE + ml * OSM_PITCH + n * 2) = tl;
                }
        }
    }

    // ---- phase 2 ----
    const int ar2 = warp_m * 32 + ((lane >> 3) & 1) * 8 + (lane & 7);
    const uint32_t la2 = sb + F2C_O_OFF + ar2 * OSM_PITCH + ((lane >> 4) * 8) * 2;
    const int br2 = warp_n * 32 + ((lane >> 4) << 3) + (lane & 7);
    const uint32_t lbo2 = (uint32_t)(br2 * 80 + (((lane >> 3) & 1) * 8) * 2);

    // row bookkeeping
    int mrow[2][2], tokr[2][2], slotr[2][2];
#pragma unroll
    for (int mf = 0; mf < 2; mf++)
#pragma unroll
        for (int hr = 0; hr < 2; hr++) {
            const int m = m0 + warp_m * 32 + mf * 16 + (lane >> 2) + hr * 8;
            mrow[mf][hr] = m;
            tokr[mf][hr] = (m < cnt) ? g_tok[e * NTOK + m] : 0;
            slotr[mf][hr] = (m < cnt) ? g_slot[e * NTOK + m] : 0;
        }

    for (int s = 0; s < 4; s++) {
        const uint32_t buf = sb + ((s & 1) ? F2C_P_OFF : F2C_B_OFF);
        CP_WAIT0();
        __syncthreads();   // buf[s] ready; all warps done with buf[s-2]'s region
        if (s + 1 < 4) {
            load_wm(s + 1, sb + (((s + 1) & 1) ? F2C_P_OFF : F2C_B_OFF));
            CP_COMMIT();
        }

        const int n0 = s * 128;
        float acc2[2][4][4] = {};
#pragma unroll
        for (int ch = 0; ch < 2; ch++) {
#pragma unroll
            for (int kk = 0; kk < 2; kk++) {
                uint32_t bh[8], bl[8];
                ldmx4(bh,     buf + lbo2 + ch * 20480 + kk * 32);
                ldmx4(bh + 4, buf + lbo2 + ch * 20480 + 1280 + kk * 32);
                ldmx4(bl,     buf + lbo2 + ch * 20480 + 10240 + kk * 32);
                ldmx4(bl + 4, buf + lbo2 + ch * 20480 + 10240 + 1280 + kk * 32);
#pragma unroll
                for (int mf = 0; mf < 2; mf++) {
                    uint32_t ah[4], al[4];
                    ldmx4(ah, la2 + (uint32_t)(mf * 16 * OSM_PITCH) + ch * 64 + kk * 32);
                    ldmx4(al, la2 + OSM_PLANE + (uint32_t)(mf * 16 * OSM_PITCH) + ch * 64 + kk * 32);
#pragma unroll
                    for (int nf = 0; nf < 4; nf++)
                        mma16816(acc2[mf][nf], ah, bh[2 * nf], bh[2 * nf + 1]);
#pragma unroll
                    for (int nf = 0; nf < 4; nf++)
                        mma16816(acc2[mf][nf], ah, bl[2 * nf], bl[2 * nf + 1]);
#pragma unroll
                    for (int nf = 0; nf < 4; nf++)
                        mma16816(acc2[mf][nf], al, bh[2 * nf], bh[2 * nf + 1]);
                }
            }
        }

        // epilogue: partial stores (same mapping/values as before)
#pragma unroll
        for (int mf = 0; mf < 2; mf++)
#pragma unroll
            for (int hr = 0; hr < 2; hr++) {
                if (mrow[mf][hr] < cnt) {
                    float* yr = g_part + ((size_t)slotr[mf][hr] * NTOK + tokr[mf][hr]) * TOUT + n0;
#pragma unroll
                    for (int nf = 0; nf < 4; nf++) {
                        const int n = warp_n * 32 + nf * 8 + 2 * (lane & 3);
                        float2 v;
                        v.x = acc2[mf][nf][2 * hr + 0];
                        v.y = acc2[mf][nf][2 * hr + 1];
                        *(float2*)(yr + n) = v;
                    }
                }
            }
    }
}

// ---------------- kernel 5: finish — y = p0 + p1, EPS fixup; reset g_cnt ----------------
__global__ void finish_kernel(float4* __restrict__ y) {
    if (blockIdx.x == 0 && threadIdx.x < NEXP) g_cnt[threadIdx.x] = 0;  // clean for next launch
    const int n = NTOK * TOUT / 4;
    const float4* p0 = (const float4*)g_part;
    const float4* p1 = (const float4*)(g_part + (size_t)NTOK * TOUT);
    for (int i = blockIdx.x * blockDim.x + threadIdx.x; i < n;
         i += gridDim.x * blockDim.x) {
        const float4 a = p0[i];
        const float4 b = p1[i];
        float4 v;
        v.x = a.x + b.x; v.y = a.y + b.y; v.z = a.z + b.z; v.w = a.w + b.w;
        if (v.x == 0.f) v.x = EPSV;
        if (v.y == 0.f) v.y = EPSV;
        if (v.z == 0.f) v.z = EPSV;
        if (v.w == 0.f) v.w = EPSV;
        y[i] = v;
    }
}

// ---------------- launch ----------------
extern "C" void kernel_launch(void* const* d_in, const int* in_sizes, int n_in,
                              void* d_out, int out_size) {
    const float* x  = (const float*)d_in[0];
    // d_in[1] = labels (int64) — unused by the reference computation
    const float* wg = (const float*)d_in[2];
    const float* W1 = (const float*)d_in[3];
    const float* b1 = (const float*)d_in[4];
    const float* W2 = (const float*)d_in[5];
    const float* b2 = (const float*)d_in[6];
    const float* Wm = (const float*)d_in[7];
    float* y = (float*)d_out;

    cudaFuncSetAttribute(fc1_mma,    cudaFuncAttributeMaxDynamicSharedMemorySize, SMEM_FC1);
    cudaFuncSetAttribute(fc2cmb_mma, cudaFuncAttributeMaxDynamicSharedMemorySize, SMEM_F2C);

    prep_kernel<<<NTOK / 8 + 512, 256>>>(x, wg, W1, W2, Wm);

    dim3 g1(NTOK / 128, HDIM / 128, NEXP);  // (64, 2, 8)
    fc1_mma<<<g1, 256, SMEM_FC1>>>(b1);

    dim3 g2(NTOK / 64, 1, NEXP);            // (128, 1, 8)
    fc2cmb_mma<<<g2, 256, SMEM_F2C>>>(b2);

    finish_kernel<<<512, 256>>>((float4*)y);
}